// round 1
// baseline (speedup 1.0000x reference)
#include <cuda_runtime.h>

#define DM 1024
#define NH 16
#define HD 64
#define BB 2
#define LL 2048
#define ML (BB * LL)  // 4096 total rows

// ---------------- scratch (no allocation allowed) ----------------
__device__ float g_qp[ML * DM];
__device__ float g_kp[ML * DM];
__device__ float g_vp[ML * DM];
__device__ float g_at[ML * DM];

// =================================================================
// GEMM:  Y[M,N] = X[M,K] @ W[N,K]^T + bias[N]
// 128x128 tile, BK=16, 256 threads, 8x8 per thread.
// =================================================================
__global__ __launch_bounds__(256)
void gemm_xwt_bias(const float* __restrict__ X, const float* __restrict__ W,
                   const float* __restrict__ bias, float* __restrict__ Y,
                   int M, int N, int K)
{
    __shared__ float As[16][128];
    __shared__ float Bs[16][128];

    const int bm = blockIdx.y * 128;
    const int bn = blockIdx.x * 128;
    const int tid = threadIdx.x;
    const int lr = tid >> 2;          // 0..63
    const int lc = (tid & 3) << 2;    // 0,4,8,12
    const int trf = (tid >> 4) << 3;  // 0..120
    const int tcf = (tid & 15) << 3;  // 0..120

    float acc[8][8];
#pragma unroll
    for (int i = 0; i < 8; i++)
#pragma unroll
        for (int j = 0; j < 8; j++) acc[i][j] = 0.f;

    for (int k0 = 0; k0 < K; k0 += 16) {
#pragma unroll
        for (int h = 0; h < 2; h++) {
            int row = lr + h * 64;
            float4 xa = *reinterpret_cast<const float4*>(X + (size_t)(bm + row) * K + k0 + lc);
            As[lc + 0][row] = xa.x; As[lc + 1][row] = xa.y;
            As[lc + 2][row] = xa.z; As[lc + 3][row] = xa.w;
            float4 wa = *reinterpret_cast<const float4*>(W + (size_t)(bn + row) * K + k0 + lc);
            Bs[lc + 0][row] = wa.x; Bs[lc + 1][row] = wa.y;
            Bs[lc + 2][row] = wa.z; Bs[lc + 3][row] = wa.w;
        }
        __syncthreads();
#pragma unroll
        for (int kk = 0; kk < 16; kk++) {
            float4 a0 = *reinterpret_cast<const float4*>(&As[kk][trf]);
            float4 a1 = *reinterpret_cast<const float4*>(&As[kk][trf + 4]);
            float4 b0 = *reinterpret_cast<const float4*>(&Bs[kk][tcf]);
            float4 b1 = *reinterpret_cast<const float4*>(&Bs[kk][tcf + 4]);
            float ra[8] = {a0.x, a0.y, a0.z, a0.w, a1.x, a1.y, a1.z, a1.w};
            float rb[8] = {b0.x, b0.y, b0.z, b0.w, b1.x, b1.y, b1.z, b1.w};
#pragma unroll
            for (int i = 0; i < 8; i++)
#pragma unroll
                for (int j = 0; j < 8; j++)
                    acc[i][j] = fmaf(ra[i], rb[j], acc[i][j]);
        }
        __syncthreads();
    }

#pragma unroll
    for (int i = 0; i < 8; i++) {
        size_t row = (size_t)(bm + trf + i);
        float* yp = Y + row * N + bn + tcf;
        const float* bp = bias + bn + tcf;
        float4 o0, o1;
        o0.x = acc[i][0] + bp[0]; o0.y = acc[i][1] + bp[1];
        o0.z = acc[i][2] + bp[2]; o0.w = acc[i][3] + bp[3];
        o1.x = acc[i][4] + bp[4]; o1.y = acc[i][5] + bp[5];
        o1.z = acc[i][6] + bp[6]; o1.w = acc[i][7] + bp[7];
        *reinterpret_cast<float4*>(yp) = o0;
        *reinterpret_cast<float4*>(yp + 4) = o1;
    }
}

// =================================================================
// Flash attention, fp32.
// Per block: one (b, h, 128-query tile). 256 threads = 16x16 grid,
// each thread owns an 8(row) x 4(col/dim) register tile.
// Q and K stored d-major in smem for LDS.128-friendly inner loops.
// =================================================================
#define BR 128
#define BC 64
#define QST_S 132  // [HD][BR+pad]
#define KST_S 68   // [HD][BC+pad]
#define VS_S 68    // [BC][HD+pad]
#define PS_S 68    // [BR][BC+pad]
#define FLASH_SMEM_FLOATS (HD * QST_S + HD * KST_S + BC * VS_S + BR * PS_S)
#define FLASH_SMEM_BYTES (FLASH_SMEM_FLOATS * 4)

__global__ __launch_bounds__(256, 1)
void flash_kernel(const float* __restrict__ Qp, const float* __restrict__ Kp,
                  const float* __restrict__ Vp, const int* __restrict__ mask,
                  float* __restrict__ Op)
{
    extern __shared__ float sm[];
    float* Qst = sm;                  // [HD][QST_S]   (d-major)
    float* Kst = Qst + HD * QST_S;    // [HD][KST_S]   (d-major)
    float* Vs  = Kst + HD * KST_S;    // [BC][VS_S]    (key-major)
    float* Ps  = Vs + BC * VS_S;      // [BR][PS_S]

    const int qt = blockIdx.x;
    const int h  = blockIdx.y;
    const int b  = blockIdx.z;
    const int tid = threadIdx.x;
    const int tr = tid >> 4;   // 0..15 -> rows tr*8..tr*8+7
    const int tc = tid & 15;   // 0..15 -> cols/dims tc*4..tc*4+3

    const size_t base = (size_t)b * LL * DM + (size_t)h * HD;
    const int mbase = b * LL;

    // ---- load Q tile (transposed to d-major) ----
    for (int i = tid; i < BR * (HD / 4); i += 256) {
        int row = i >> 4;
        int c4 = (i & 15) << 2;
        float4 qv = *reinterpret_cast<const float4*>(Qp + base + (size_t)(qt * BR + row) * DM + c4);
        Qst[(c4 + 0) * QST_S + row] = qv.x;
        Qst[(c4 + 1) * QST_S + row] = qv.y;
        Qst[(c4 + 2) * QST_S + row] = qv.z;
        Qst[(c4 + 3) * QST_S + row] = qv.w;
    }

    float m_i[8], l_i[8], acc[8][4];
#pragma unroll
    for (int i = 0; i < 8; i++) {
        m_i[i] = -3.0e38f;
        l_i[i] = 0.f;
#pragma unroll
        for (int j = 0; j < 4; j++) acc[i][j] = 0.f;
    }

    for (int kt = 0; kt < LL / BC; kt++) {
        __syncthreads();  // protect Kst/Vs from previous iteration readers
        // ---- load K (transposed to d-major) and V tiles ----
        for (int i = tid; i < BC * (HD / 4); i += 256) {
            int row = i >> 4;
            int c4 = (i & 15) << 2;
            size_t g = base + (size_t)(kt * BC + row) * DM + c4;
            float4 kv4 = *reinterpret_cast<const float4*>(Kp + g);
            Kst[(c4 + 0) * KST_S + row] = kv4.x;
            Kst[(c4 + 1) * KST_S + row] = kv4.y;
            Kst[(c4 + 2) * KST_S + row] = kv4.z;
            Kst[(c4 + 3) * KST_S + row] = kv4.w;
            float4 vv4 = *reinterpret_cast<const float4*>(Vp + g);
            *reinterpret_cast<float4*>(&Vs[row * VS_S + c4]) = vv4;
        }
        __syncthreads();

        // ---- S = Q K^T (8x4 per thread) ----
        float s[8][4];
#pragma unroll
        for (int i = 0; i < 8; i++)
#pragma unroll
            for (int j = 0; j < 4; j++) s[i][j] = 0.f;

#pragma unroll 8
        for (int d = 0; d < HD; d++) {
            float4 kf = *reinterpret_cast<const float4*>(&Kst[d * KST_S + tc * 4]);
            const float* qrow = &Qst[d * QST_S + tr * 8];
            float4 qa = *reinterpret_cast<const float4*>(qrow);
            float4 qb = *reinterpret_cast<const float4*>(qrow + 4);
            float qv[8] = {qa.x, qa.y, qa.z, qa.w, qb.x, qb.y, qb.z, qb.w};
            float kv[4] = {kf.x, kf.y, kf.z, kf.w};
#pragma unroll
            for (int i = 0; i < 8; i++)
#pragma unroll
                for (int j = 0; j < 4; j++)
                    s[i][j] = fmaf(qv[i], kv[j], s[i][j]);
        }

        // ---- mask + online softmax update ----
        float madd[4];
#pragma unroll
        for (int j = 0; j < 4; j++)
            madd[j] = mask[mbase + kt * BC + tc * 4 + j] ? -1e15f : 0.f;

#pragma unroll
        for (int i = 0; i < 8; i++) {
            float mx = -3.0e38f;
#pragma unroll
            for (int j = 0; j < 4; j++) {
                s[i][j] = s[i][j] * 0.125f + madd[j];
                mx = fmaxf(mx, s[i][j]);
            }
#pragma unroll
            for (int o = 8; o >= 1; o >>= 1)
                mx = fmaxf(mx, __shfl_xor_sync(0xffffffffu, mx, o));
            float mnew = fmaxf(m_i[i], mx);
            float corr = __expf(m_i[i] - mnew);
            float rsum = 0.f;
#pragma unroll
            for (int j = 0; j < 4; j++) {
                float p = __expf(s[i][j] - mnew);
                s[i][j] = p;
                rsum += p;
            }
#pragma unroll
            for (int o = 8; o >= 1; o >>= 1)
                rsum += __shfl_xor_sync(0xffffffffu, rsum, o);
            l_i[i] = l_i[i] * corr + rsum;
            m_i[i] = mnew;
#pragma unroll
            for (int j = 0; j < 4; j++) acc[i][j] *= corr;
            // write P row chunk (float4, aligned: stride 68*4B, offset 16*tc B)
            *reinterpret_cast<float4*>(&Ps[(tr * 8 + i) * PS_S + tc * 4]) =
                make_float4(s[i][0], s[i][1], s[i][2], s[i][3]);
        }
        __syncthreads();

        // ---- acc += P @ V ----
#pragma unroll 4
        for (int c = 0; c < BC; c++) {
            float4 vf = *reinterpret_cast<const float4*>(&Vs[c * VS_S + tc * 4]);
            float vv[4] = {vf.x, vf.y, vf.z, vf.w};
#pragma unroll
            for (int i = 0; i < 8; i++) {
                float p = Ps[(tr * 8 + i) * PS_S + c];
#pragma unroll
                for (int j = 0; j < 4; j++)
                    acc[i][j] = fmaf(p, vv[j], acc[i][j]);
            }
        }
    }

    // ---- normalize + write out in [B, L, D] layout (heads recombined) ----
#pragma unroll
    for (int i = 0; i < 8; i++) {
        float inv = 1.f / l_i[i];
        size_t row = (size_t)b * LL + (size_t)qt * BR + tr * 8 + i;
        float* op = Op + row * DM + h * HD + tc * 4;
        *reinterpret_cast<float4*>(op) =
            make_float4(acc[i][0] * inv, acc[i][1] * inv, acc[i][2] * inv, acc[i][3] * inv);
    }
}

// =================================================================
// launch
// =================================================================
extern "C" void kernel_launch(void* const* d_in, const int* in_sizes, int n_in,
                              void* d_out, int out_size)
{
    const float* q    = (const float*)d_in[0];
    const float* k    = (const float*)d_in[1];
    const float* v    = (const float*)d_in[2];
    const int*   mask = (const int*)d_in[3];
    const float* Wq   = (const float*)d_in[4];
    const float* bq   = (const float*)d_in[5];
    const float* Wk   = (const float*)d_in[6];
    const float* bk   = (const float*)d_in[7];
    const float* Wv   = (const float*)d_in[8];
    const float* bv   = (const float*)d_in[9];
    const float* Wo   = (const float*)d_in[10];
    const float* bo   = (const float*)d_in[11];

    float *gq, *gk, *gv, *ga;
    cudaGetSymbolAddress((void**)&gq, g_qp);
    cudaGetSymbolAddress((void**)&gk, g_kp);
    cudaGetSymbolAddress((void**)&gv, g_vp);
    cudaGetSymbolAddress((void**)&ga, g_at);

    dim3 gg(DM / 128, ML / 128);  // (8, 32)

    gemm_xwt_bias<<<gg, 256>>>(q, Wq, bq, gq, ML, DM, DM);
    gemm_xwt_bias<<<gg, 256>>>(k, Wk, bk, gk, ML, DM, DM);
    gemm_xwt_bias<<<gg, 256>>>(v, Wv, bv, gv, ML, DM, DM);

    cudaFuncSetAttribute(flash_kernel, cudaFuncAttributeMaxDynamicSharedMemorySize,
                         FLASH_SMEM_BYTES);
    flash_kernel<<<dim3(LL / BR, NH, BB), 256, FLASH_SMEM_BYTES>>>(gq, gk, gv, mask, ga);

    gemm_xwt_bias<<<gg, 256>>>(ga, Wo, bo, (float*)d_out, ML, DM, DM);
}

// round 4
// speedup vs baseline: 1.6443x; 1.6443x over previous
#include <cuda_runtime.h>
#include <cuda_bf16.h>
#include <cstdint>

#define DM 1024
#define NH 16
#define HD 64
#define BB 2
#define LL 2048
#define ML (BB * LL)  // 4096 total rows

// ---------------- scratch (no allocation allowed) ----------------
__device__ float g_qp[ML * DM];
__device__ float g_kp[ML * DM];
__device__ float g_vp[ML * DM];
__device__ float g_at[ML * DM];
__device__ __nv_bfloat16 g_xhi[ML * DM];
__device__ __nv_bfloat16 g_xlo[ML * DM];
__device__ __nv_bfloat16 g_whi[DM * DM];
__device__ __nv_bfloat16 g_wlo[DM * DM];

// ================= warp-MMA helpers (base compute_103 PTX only) ==========
__device__ __forceinline__ uint32_t smem_u32(const void* p) {
    uint32_t a;
    asm("{ .reg .u64 t; cvta.to.shared.u64 t, %1; cvt.u32.u64 %0, t; }" : "=r"(a) : "l"(p));
    return a;
}
__device__ __forceinline__ void ldm_x4(uint32_t* r, uint32_t addr) {
    asm volatile("ldmatrix.sync.aligned.m8n8.x4.shared.b16 {%0,%1,%2,%3}, [%4];"
                 : "=r"(r[0]), "=r"(r[1]), "=r"(r[2]), "=r"(r[3]) : "r"(addr));
}
__device__ __forceinline__ void ldm_x2(uint32_t* r, uint32_t addr) {
    asm volatile("ldmatrix.sync.aligned.m8n8.x2.shared.b16 {%0,%1}, [%2];"
                 : "=r"(r[0]), "=r"(r[1]) : "r"(addr));
}
__device__ __forceinline__ void mma16816(float* c, const uint32_t* a, const uint32_t* b) {
    asm volatile("mma.sync.aligned.m16n8k16.row.col.f32.bf16.bf16.f32 "
                 "{%0,%1,%2,%3}, {%4,%5,%6,%7}, {%8,%9}, {%0,%1,%2,%3};"
                 : "+f"(c[0]), "+f"(c[1]), "+f"(c[2]), "+f"(c[3])
                 : "r"(a[0]), "r"(a[1]), "r"(a[2]), "r"(a[3]), "r"(b[0]), "r"(b[1]));
}

// =================================================================
// split fp32 -> bf16 hi/lo
// =================================================================
__global__ __launch_bounds__(256)
void split_bf16(const float* __restrict__ x, __nv_bfloat16* __restrict__ hi,
                __nv_bfloat16* __restrict__ lo, int n)
{
    int i = (blockIdx.x * 256 + threadIdx.x) * 4;
    if (i >= n) return;
    float4 f = *reinterpret_cast<const float4*>(x + i);
    __nv_bfloat16 h0 = __float2bfloat16(f.x);
    __nv_bfloat16 h1 = __float2bfloat16(f.y);
    __nv_bfloat16 h2 = __float2bfloat16(f.z);
    __nv_bfloat16 h3 = __float2bfloat16(f.w);
    __nv_bfloat16 l0 = __float2bfloat16(f.x - __bfloat162float(h0));
    __nv_bfloat16 l1 = __float2bfloat16(f.y - __bfloat162float(h1));
    __nv_bfloat16 l2 = __float2bfloat16(f.z - __bfloat162float(h2));
    __nv_bfloat16 l3 = __float2bfloat16(f.w - __bfloat162float(h3));
    *reinterpret_cast<__nv_bfloat162*>(hi + i)     = __nv_bfloat162(h0, h1);
    *reinterpret_cast<__nv_bfloat162*>(hi + i + 2) = __nv_bfloat162(h2, h3);
    *reinterpret_cast<__nv_bfloat162*>(lo + i)     = __nv_bfloat162(l0, l1);
    *reinterpret_cast<__nv_bfloat162*>(lo + i + 2) = __nv_bfloat162(l2, l3);
}

// =================================================================
// mma.sync GEMM: Y[M,N] = (Xhi+Xlo)[M,K] @ (Whi+Wlo)[N,K]^T + bias
// 128x128 CTA tile, 8 warps (2x4), warp tile 64x32, K-chunk 32.
// 3 passes: hi*hi + hi*lo + lo*hi (lo*lo negligible ~2^-18).
// =================================================================
#define LDK 40  // 32 + 8 pad, keeps ldmatrix rows 16B aligned

__global__ __launch_bounds__(256)
void gemm_mma(const __nv_bfloat16* __restrict__ Ahi, const __nv_bfloat16* __restrict__ Alo,
              const __nv_bfloat16* __restrict__ Bhi, const __nv_bfloat16* __restrict__ Blo,
              const float* __restrict__ bias, float* __restrict__ Y,
              int M, int N, int K)
{
    __shared__ __nv_bfloat16 sAh[128 * LDK];
    __shared__ __nv_bfloat16 sAl[128 * LDK];
    __shared__ __nv_bfloat16 sBh[128 * LDK];
    __shared__ __nv_bfloat16 sBl[128 * LDK];

    const int tid  = threadIdx.x;
    const int lane = tid & 31;
    const int wid  = tid >> 5;
    const int wm   = wid & 1;   // 0..1 -> M offset 0/64
    const int wn   = wid >> 1;  // 0..3 -> N offset 0/32/64/96
    const int bm   = blockIdx.y * 128;
    const int bn   = blockIdx.x * 128;

    const uint32_t uAh = smem_u32(sAh);
    const uint32_t uAl = smem_u32(sAl);
    const uint32_t uBh = smem_u32(sBh);
    const uint32_t uBl = smem_u32(sBl);

    float acc[4][4][4];
#pragma unroll
    for (int mt = 0; mt < 4; mt++)
#pragma unroll
        for (int nt = 0; nt < 4; nt++)
#pragma unroll
            for (int e = 0; e < 4; e++) acc[mt][nt][e] = 0.f;

    // precomputed ldmatrix lane offsets (bytes)
    const uint32_t aoff = (uint32_t)(((lane & 15) * LDK + (lane >> 4) * 8) * 2);
    const uint32_t boff = (uint32_t)(((lane & 7) * LDK + ((lane >> 3) & 1) * 8) * 2);

    for (int k0 = 0; k0 < K; k0 += 32) {
        __syncthreads();
#pragma unroll
        for (int i = tid; i < 512; i += 256) {
            int row = i >> 2;
            int seg = (i & 3) << 3;
            size_t ga = (size_t)(bm + row) * K + k0 + seg;
            size_t gb = (size_t)(bn + row) * K + k0 + seg;
            *reinterpret_cast<float4*>(&sAh[row * LDK + seg]) = *reinterpret_cast<const float4*>(Ahi + ga);
            *reinterpret_cast<float4*>(&sAl[row * LDK + seg]) = *reinterpret_cast<const float4*>(Alo + ga);
            *reinterpret_cast<float4*>(&sBh[row * LDK + seg]) = *reinterpret_cast<const float4*>(Bhi + gb);
            *reinterpret_cast<float4*>(&sBl[row * LDK + seg]) = *reinterpret_cast<const float4*>(Blo + gb);
        }
        __syncthreads();

#pragma unroll
        for (int ks = 0; ks < 2; ks++) {
            const uint32_t kb = (uint32_t)(ks * 16 * 2);
            uint32_t ah[4][4], al[4][4], bh[4][2], bl[4][2];
#pragma unroll
            for (int mt = 0; mt < 4; mt++) {
                uint32_t r = (uint32_t)((wm * 64 + mt * 16) * LDK * 2) + aoff + kb;
                ldm_x4(ah[mt], uAh + r);
                ldm_x4(al[mt], uAl + r);
            }
#pragma unroll
            for (int nt = 0; nt < 4; nt++) {
                uint32_t r = (uint32_t)((wn * 32 + nt * 8) * LDK * 2) + boff + kb;
                ldm_x2(bh[nt], uBh + r);
                ldm_x2(bl[nt], uBl + r);
            }
#pragma unroll
            for (int mt = 0; mt < 4; mt++)
#pragma unroll
                for (int nt = 0; nt < 4; nt++) {
                    mma16816(acc[mt][nt], ah[mt], bh[nt]);
                    mma16816(acc[mt][nt], ah[mt], bl[nt]);
                    mma16816(acc[mt][nt], al[mt], bh[nt]);
                }
        }
    }

    // epilogue: c0,c1 -> (row, col..col+1), c2,c3 -> (row+8, ...)
#pragma unroll
    for (int mt = 0; mt < 4; mt++) {
        int r0 = bm + wm * 64 + mt * 16 + (lane >> 2);
#pragma unroll
        for (int nt = 0; nt < 4; nt++) {
            int c0 = bn + wn * 32 + nt * 8 + (lane & 3) * 2;
            float bx = bias[c0], by = bias[c0 + 1];
            float2 o0 = make_float2(acc[mt][nt][0] + bx, acc[mt][nt][1] + by);
            float2 o1 = make_float2(acc[mt][nt][2] + bx, acc[mt][nt][3] + by);
            *reinterpret_cast<float2*>(Y + (size_t)r0 * N + c0) = o0;
            *reinterpret_cast<float2*>(Y + (size_t)(r0 + 8) * N + c0) = o1;
        }
    }
}

// =================================================================
// Flash attention, fp32 (occupancy 2)
// =================================================================
#define BR 128
#define BC 64
#define QST_S 132
#define KST_S 68
#define VS_S 68
#define PS_S 68
#define FLASH_SMEM_FLOATS (HD * QST_S + HD * KST_S + BC * VS_S + BR * PS_S)
#define FLASH_SMEM_BYTES (FLASH_SMEM_FLOATS * 4)

__global__ __launch_bounds__(256, 2)
void flash_kernel(const float* __restrict__ Qp, const float* __restrict__ Kp,
                  const float* __restrict__ Vp, const int* __restrict__ mask,
                  float* __restrict__ Op)
{
    extern __shared__ float sm[];
    float* Qst = sm;
    float* Kst = Qst + HD * QST_S;
    float* Vs  = Kst + HD * KST_S;
    float* Ps  = Vs + BC * VS_S;

    const int qt = blockIdx.x;
    const int h  = blockIdx.y;
    const int b  = blockIdx.z;
    const int tid = threadIdx.x;
    const int tr = tid >> 4;
    const int tc = tid & 15;

    const size_t base = (size_t)b * LL * DM + (size_t)h * HD;
    const int mbase = b * LL;

    for (int i = tid; i < BR * (HD / 4); i += 256) {
        int row = i >> 4;
        int c4 = (i & 15) << 2;
        float4 qv = *reinterpret_cast<const float4*>(Qp + base + (size_t)(qt * BR + row) * DM + c4);
        Qst[(c4 + 0) * QST_S + row] = qv.x;
        Qst[(c4 + 1) * QST_S + row] = qv.y;
        Qst[(c4 + 2) * QST_S + row] = qv.z;
        Qst[(c4 + 3) * QST_S + row] = qv.w;
    }

    float m_i[8], l_i[8], acc[8][4];
#pragma unroll
    for (int i = 0; i < 8; i++) {
        m_i[i] = -3.0e38f;
        l_i[i] = 0.f;
#pragma unroll
        for (int j = 0; j < 4; j++) acc[i][j] = 0.f;
    }

    for (int kt = 0; kt < LL / BC; kt++) {
        __syncthreads();
        for (int i = tid; i < BC * (HD / 4); i += 256) {
            int row = i >> 4;
            int c4 = (i & 15) << 2;
            size_t g = base + (size_t)(kt * BC + row) * DM + c4;
            float4 kv4 = *reinterpret_cast<const float4*>(Kp + g);
            Kst[(c4 + 0) * KST_S + row] = kv4.x;
            Kst[(c4 + 1) * KST_S + row] = kv4.y;
            Kst[(c4 + 2) * KST_S + row] = kv4.z;
            Kst[(c4 + 3) * KST_S + row] = kv4.w;
            float4 vv4 = *reinterpret_cast<const float4*>(Vp + g);
            *reinterpret_cast<float4*>(&Vs[row * VS_S + c4]) = vv4;
        }
        __syncthreads();

        float s[8][4];
#pragma unroll
        for (int i = 0; i < 8; i++)
#pragma unroll
            for (int j = 0; j < 4; j++) s[i][j] = 0.f;

#pragma unroll 8
        for (int d = 0; d < HD; d++) {
            float4 kf = *reinterpret_cast<const float4*>(&Kst[d * KST_S + tc * 4]);
            const float* qrow = &Qst[d * QST_S + tr * 8];
            float4 qa = *reinterpret_cast<const float4*>(qrow);
            float4 qb = *reinterpret_cast<const float4*>(qrow + 4);
            float qv[8] = {qa.x, qa.y, qa.z, qa.w, qb.x, qb.y, qb.z, qb.w};
            float kv[4] = {kf.x, kf.y, kf.z, kf.w};
#pragma unroll
            for (int i = 0; i < 8; i++)
#pragma unroll
                for (int j = 0; j < 4; j++)
                    s[i][j] = fmaf(qv[i], kv[j], s[i][j]);
        }

        float madd[4];
#pragma unroll
        for (int j = 0; j < 4; j++)
            madd[j] = mask[mbase + kt * BC + tc * 4 + j] ? -1e15f : 0.f;

#pragma unroll
        for (int i = 0; i < 8; i++) {
            float mx = -3.0e38f;
#pragma unroll
            for (int j = 0; j < 4; j++) {
                s[i][j] = s[i][j] * 0.125f + madd[j];
                mx = fmaxf(mx, s[i][j]);
            }
#pragma unroll
            for (int o = 8; o >= 1; o >>= 1)
                mx = fmaxf(mx, __shfl_xor_sync(0xffffffffu, mx, o));
            float mnew = fmaxf(m_i[i], mx);
            float corr = __expf(m_i[i] - mnew);
            float rsum = 0.f;
#pragma unroll
            for (int j = 0; j < 4; j++) {
                float p = __expf(s[i][j] - mnew);
                s[i][j] = p;
                rsum += p;
            }
#pragma unroll
            for (int o = 8; o >= 1; o >>= 1)
                rsum += __shfl_xor_sync(0xffffffffu, rsum, o);
            l_i[i] = l_i[i] * corr + rsum;
            m_i[i] = mnew;
#pragma unroll
            for (int j = 0; j < 4; j++) acc[i][j] *= corr;
            *reinterpret_cast<float4*>(&Ps[(tr * 8 + i) * PS_S + tc * 4]) =
                make_float4(s[i][0], s[i][1], s[i][2], s[i][3]);
        }
        __syncthreads();

#pragma unroll 4
        for (int c = 0; c < BC; c++) {
            float4 vf = *reinterpret_cast<const float4*>(&Vs[c * VS_S + tc * 4]);
            float vv[4] = {vf.x, vf.y, vf.z, vf.w};
#pragma unroll
            for (int i = 0; i < 8; i++) {
                float p = Ps[(tr * 8 + i) * PS_S + c];
#pragma unroll
                for (int j = 0; j < 4; j++)
                    acc[i][j] = fmaf(p, vv[j], acc[i][j]);
            }
        }
    }

#pragma unroll
    for (int i = 0; i < 8; i++) {
        float inv = 1.f / l_i[i];
        size_t row = (size_t)b * LL + (size_t)qt * BR + tr * 8 + i;
        float* op = Op + row * DM + h * HD + tc * 4;
        *reinterpret_cast<float4*>(op) =
            make_float4(acc[i][0] * inv, acc[i][1] * inv, acc[i][2] * inv, acc[i][3] * inv);
    }
}

// =================================================================
// launch
// =================================================================
extern "C" void kernel_launch(void* const* d_in, const int* in_sizes, int n_in,
                              void* d_out, int out_size)
{
    const float* q    = (const float*)d_in[0];
    const float* k    = (const float*)d_in[1];
    const float* v    = (const float*)d_in[2];
    const int*   mask = (const int*)d_in[3];
    const float* Wq   = (const float*)d_in[4];
    const float* bq   = (const float*)d_in[5];
    const float* Wk   = (const float*)d_in[6];
    const float* bk   = (const float*)d_in[7];
    const float* Wv   = (const float*)d_in[8];
    const float* bv   = (const float*)d_in[9];
    const float* Wo   = (const float*)d_in[10];
    const float* bo   = (const float*)d_in[11];

    float *gq, *gk, *gv, *ga;
    __nv_bfloat16 *xhi, *xlo, *whi, *wlo;
    cudaGetSymbolAddress((void**)&gq, g_qp);
    cudaGetSymbolAddress((void**)&gk, g_kp);
    cudaGetSymbolAddress((void**)&gv, g_vp);
    cudaGetSymbolAddress((void**)&ga, g_at);
    cudaGetSymbolAddress((void**)&xhi, g_xhi);
    cudaGetSymbolAddress((void**)&xlo, g_xlo);
    cudaGetSymbolAddress((void**)&whi, g_whi);
    cudaGetSymbolAddress((void**)&wlo, g_wlo);

    cudaFuncSetAttribute(flash_kernel, cudaFuncAttributeMaxDynamicSharedMemorySize,
                         FLASH_SMEM_BYTES);

    const int NX = ML * DM;
    const int NW = DM * DM;
    dim3 gg(DM / 128, ML / 128);  // (8, 32)

    // Q projection
    split_bf16<<<NX / 1024, 256>>>(q, xhi, xlo, NX);
    split_bf16<<<NW / 1024, 256>>>(Wq, whi, wlo, NW);
    gemm_mma<<<gg, 256>>>(xhi, xlo, whi, wlo, bq, gq, ML, DM, DM);
    // K projection
    split_bf16<<<NX / 1024, 256>>>(k, xhi, xlo, NX);
    split_bf16<<<NW / 1024, 256>>>(Wk, whi, wlo, NW);
    gemm_mma<<<gg, 256>>>(xhi, xlo, whi, wlo, bk, gk, ML, DM, DM);
    // V projection
    split_bf16<<<NX / 1024, 256>>>(v, xhi, xlo, NX);
    split_bf16<<<NW / 1024, 256>>>(Wv, whi, wlo, NW);
    gemm_mma<<<gg, 256>>>(xhi, xlo, whi, wlo, bv, gv, ML, DM, DM);

    // attention
    flash_kernel<<<dim3(LL / BR, NH, BB), 256, FLASH_SMEM_BYTES>>>(gq, gk, gv, mask, ga);

    // output projection
    split_bf16<<<NX / 1024, 256>>>(ga, xhi, xlo, NX);
    split_bf16<<<NW / 1024, 256>>>(Wo, whi, wlo, NW);
    gemm_mma<<<gg, 256>>>(xhi, xlo, whi, wlo, bo, (float*)d_out, ML, DM, DM);
}

// round 6
// speedup vs baseline: 3.3917x; 2.0627x over previous
#include <cuda_runtime.h>
#include <cuda_bf16.h>
#include <cstdint>

#define DM 1024
#define NH 16
#define HD 64
#define BB 2
#define LL 2048
#define ML (BB * LL)  // 4096 total rows

// ---------------- scratch (no allocation allowed) ----------------
__device__ float g_qp[ML * DM];
__device__ float g_kp[ML * DM];
__device__ float g_vp[ML * DM];
__device__ float g_at[ML * DM];
__device__ __nv_bfloat16 g_xhi[ML * DM];
__device__ __nv_bfloat16 g_xlo[ML * DM];
__device__ __nv_bfloat16 g_whi[DM * DM];
__device__ __nv_bfloat16 g_wlo[DM * DM];
// flash buffers
__device__ __nv_bfloat16 g_qhi[ML * DM];
__device__ __nv_bfloat16 g_qlo[ML * DM];
__device__ __nv_bfloat16 g_kchi[BB * NH * LL * HD];
__device__ __nv_bfloat16 g_kclo[BB * NH * LL * HD];
__device__ __nv_bfloat16 g_vthi[BB * NH * HD * LL];
__device__ __nv_bfloat16 g_vtlo[BB * NH * HD * LL];
__device__ int g_cidx[BB * LL];
__device__ int g_nact[BB];

// ================= warp-MMA helpers (base compute_103 PTX only) ==========
__device__ __forceinline__ uint32_t smem_u32(const void* p) {
    uint32_t a;
    asm("{ .reg .u64 t; cvta.to.shared.u64 t, %1; cvt.u32.u64 %0, t; }" : "=r"(a) : "l"(p));
    return a;
}
__device__ __forceinline__ void ldm_x4(uint32_t* r, uint32_t addr) {
    asm volatile("ldmatrix.sync.aligned.m8n8.x4.shared.b16 {%0,%1,%2,%3}, [%4];"
                 : "=r"(r[0]), "=r"(r[1]), "=r"(r[2]), "=r"(r[3]) : "r"(addr));
}
__device__ __forceinline__ void ldm_x2(uint32_t* r, uint32_t addr) {
    asm volatile("ldmatrix.sync.aligned.m8n8.x2.shared.b16 {%0,%1}, [%2];"
                 : "=r"(r[0]), "=r"(r[1]) : "r"(addr));
}
__device__ __forceinline__ void mma16816(float* c, const uint32_t* a, const uint32_t* b) {
    asm volatile("mma.sync.aligned.m16n8k16.row.col.f32.bf16.bf16.f32 "
                 "{%0,%1,%2,%3}, {%4,%5,%6,%7}, {%8,%9}, {%0,%1,%2,%3};"
                 : "+f"(c[0]), "+f"(c[1]), "+f"(c[2]), "+f"(c[3])
                 : "r"(a[0]), "r"(a[1]), "r"(a[2]), "r"(a[3]), "r"(b[0]), "r"(b[1]));
}
__device__ __forceinline__ float ex2(float x) {
    float y;
    asm("ex2.approx.ftz.f32 %0, %1;" : "=f"(y) : "f"(x));
    return y;
}
__device__ __forceinline__ uint32_t pack2(__nv_bfloat16 a, __nv_bfloat16 b) {
    __nv_bfloat162 t = __halves2bfloat162(a, b);  // a -> low half
    return *reinterpret_cast<uint32_t*>(&t);
}

// =================================================================
// split fp32 -> bf16 hi/lo (optional scale)
// =================================================================
__global__ __launch_bounds__(256)
void split_bf16(const float* __restrict__ x, __nv_bfloat16* __restrict__ hi,
                __nv_bfloat16* __restrict__ lo, int n)
{
    int i = (blockIdx.x * 256 + threadIdx.x) * 4;
    if (i >= n) return;
    float4 f = *reinterpret_cast<const float4*>(x + i);
    __nv_bfloat16 h0 = __float2bfloat16(f.x);
    __nv_bfloat16 h1 = __float2bfloat16(f.y);
    __nv_bfloat16 h2 = __float2bfloat16(f.z);
    __nv_bfloat16 h3 = __float2bfloat16(f.w);
    __nv_bfloat16 l0 = __float2bfloat16(f.x - __bfloat162float(h0));
    __nv_bfloat16 l1 = __float2bfloat16(f.y - __bfloat162float(h1));
    __nv_bfloat16 l2 = __float2bfloat16(f.z - __bfloat162float(h2));
    __nv_bfloat16 l3 = __float2bfloat16(f.w - __bfloat162float(h3));
    *reinterpret_cast<__nv_bfloat162*>(hi + i)     = __nv_bfloat162(h0, h1);
    *reinterpret_cast<__nv_bfloat162*>(hi + i + 2) = __nv_bfloat162(h2, h3);
    *reinterpret_cast<__nv_bfloat162*>(lo + i)     = __nv_bfloat162(l0, l1);
    *reinterpret_cast<__nv_bfloat162*>(lo + i + 2) = __nv_bfloat162(l2, l3);
}

__global__ __launch_bounds__(256)
void split_bf16_scaled(const float* __restrict__ x, __nv_bfloat16* __restrict__ hi,
                       __nv_bfloat16* __restrict__ lo, int n, float sc)
{
    int i = (blockIdx.x * 256 + threadIdx.x) * 4;
    if (i >= n) return;
    float4 f = *reinterpret_cast<const float4*>(x + i);
    f.x *= sc; f.y *= sc; f.z *= sc; f.w *= sc;
    __nv_bfloat16 h0 = __float2bfloat16(f.x);
    __nv_bfloat16 h1 = __float2bfloat16(f.y);
    __nv_bfloat16 h2 = __float2bfloat16(f.z);
    __nv_bfloat16 h3 = __float2bfloat16(f.w);
    __nv_bfloat16 l0 = __float2bfloat16(f.x - __bfloat162float(h0));
    __nv_bfloat16 l1 = __float2bfloat16(f.y - __bfloat162float(h1));
    __nv_bfloat16 l2 = __float2bfloat16(f.z - __bfloat162float(h2));
    __nv_bfloat16 l3 = __float2bfloat16(f.w - __bfloat162float(h3));
    *reinterpret_cast<__nv_bfloat162*>(hi + i)     = __nv_bfloat162(h0, h1);
    *reinterpret_cast<__nv_bfloat162*>(hi + i + 2) = __nv_bfloat162(h2, h3);
    *reinterpret_cast<__nv_bfloat162*>(lo + i)     = __nv_bfloat162(l0, l1);
    *reinterpret_cast<__nv_bfloat162*>(lo + i + 2) = __nv_bfloat162(l2, l3);
}

// =================================================================
// mask compaction: indices of unmasked keys per batch (deterministic)
// =================================================================
__global__ __launch_bounds__(256)
void compact_mask(const int* __restrict__ mask, int* __restrict__ cidx,
                  int* __restrict__ nact)
{
    int b = blockIdx.x, tid = threadIdx.x;
    __shared__ int ws[256];
    const int* mb = mask + b * LL;
    int base = tid * 8;
    int loc[8];
    int cnt = 0;
#pragma unroll
    for (int i = 0; i < 8; i++) { loc[i] = cnt; cnt += (mb[base + i] == 0); }
    ws[tid] = cnt;
    __syncthreads();
    if (tid == 0) {
        int acc = 0;
        for (int i = 0; i < 256; i++) { int t = ws[i]; ws[i] = acc; acc += t; }
        nact[b] = acc;
    }
    __syncthreads();
    int off = ws[tid];
#pragma unroll
    for (int i = 0; i < 8; i++)
        if (mb[base + i] == 0) cidx[b * LL + off + loc[i]] = base + i;
}

// =================================================================
// gather compacted K (hi/lo, [bh][key][dim]) and transposed V
// (hi/lo, [bh][dim][key]) from projected fp32 K/V.
// =================================================================
__global__ __launch_bounds__(256)
void gather_kv(const float* __restrict__ Kp, const float* __restrict__ Vp,
               const int* __restrict__ cidx, const int* __restrict__ nact,
               __nv_bfloat16* __restrict__ Kchi, __nv_bfloat16* __restrict__ Kclo,
               __nv_bfloat16* __restrict__ Vthi, __nv_bfloat16* __restrict__ Vtlo)
{
    __shared__ float sv[128][65];
    const int it = blockIdx.x, h = blockIdx.y, b = blockIdx.z;
    const int bh = b * NH + h;
    const int na = nact[b];
    const int bound = (na + 63) & ~63;
    const int i0 = it * 128;
    if (i0 >= bound) return;
    const int tid = threadIdx.x;

#pragma unroll
    for (int t = 0; t < 32; t++) {
        int idx = tid + t * 256;
        int d = idx & 63, il = idx >> 6;
        int gi = i0 + il;
        float kv = 0.f, vv = 0.f;
        if (gi < na) {
            int src = cidx[b * LL + gi];
            size_t g = ((size_t)(b * LL) + src) * DM + h * HD + d;
            kv = Kp[g];
            vv = Vp[g];
        }
        __nv_bfloat16 kh = __float2bfloat16(kv);
        size_t ko = ((size_t)bh * LL + gi) * HD + d;
        Kchi[ko] = kh;
        Kclo[ko] = __float2bfloat16(kv - __bfloat162float(kh));
        sv[il][d] = vv;
    }
    __syncthreads();
#pragma unroll
    for (int t = 0; t < 32; t++) {
        int idx = tid + t * 256;
        int ii = idx & 127, d = idx >> 7;
        float v = sv[ii][d];
        __nv_bfloat16 vh = __float2bfloat16(v);
        size_t o = ((size_t)bh * HD + d) * LL + i0 + ii;
        Vthi[o] = vh;
        Vtlo[o] = __float2bfloat16(v - __bfloat162float(vh));
    }
}

// =================================================================
// mma.sync GEMM (verified in R4): Y = (Xhi+Xlo) @ (Whi+Wlo)^T + bias
// =================================================================
#define LDK 40

__global__ __launch_bounds__(256)
void gemm_mma(const __nv_bfloat16* __restrict__ Ahi, const __nv_bfloat16* __restrict__ Alo,
              const __nv_bfloat16* __restrict__ Bhi, const __nv_bfloat16* __restrict__ Blo,
              const float* __restrict__ bias, float* __restrict__ Y,
              int M, int N, int K)
{
    __shared__ __nv_bfloat16 sAh[128 * LDK];
    __shared__ __nv_bfloat16 sAl[128 * LDK];
    __shared__ __nv_bfloat16 sBh[128 * LDK];
    __shared__ __nv_bfloat16 sBl[128 * LDK];

    const int tid  = threadIdx.x;
    const int lane = tid & 31;
    const int wid  = tid >> 5;
    const int wm   = wid & 1;
    const int wn   = wid >> 1;
    const int bm   = blockIdx.y * 128;
    const int bn   = blockIdx.x * 128;

    const uint32_t uAh = smem_u32(sAh);
    const uint32_t uAl = smem_u32(sAl);
    const uint32_t uBh = smem_u32(sBh);
    const uint32_t uBl = smem_u32(sBl);

    float acc[4][4][4];
#pragma unroll
    for (int mt = 0; mt < 4; mt++)
#pragma unroll
        for (int nt = 0; nt < 4; nt++)
#pragma unroll
            for (int e = 0; e < 4; e++) acc[mt][nt][e] = 0.f;

    const uint32_t aoff = (uint32_t)(((lane & 15) * LDK + (lane >> 4) * 8) * 2);
    const uint32_t boff = (uint32_t)(((lane & 7) * LDK + ((lane >> 3) & 1) * 8) * 2);

    for (int k0 = 0; k0 < K; k0 += 32) {
        __syncthreads();
#pragma unroll
        for (int i = tid; i < 512; i += 256) {
            int row = i >> 2;
            int seg = (i & 3) << 3;
            size_t ga = (size_t)(bm + row) * K + k0 + seg;
            size_t gb = (size_t)(bn + row) * K + k0 + seg;
            *reinterpret_cast<float4*>(&sAh[row * LDK + seg]) = *reinterpret_cast<const float4*>(Ahi + ga);
            *reinterpret_cast<float4*>(&sAl[row * LDK + seg]) = *reinterpret_cast<const float4*>(Alo + ga);
            *reinterpret_cast<float4*>(&sBh[row * LDK + seg]) = *reinterpret_cast<const float4*>(Bhi + gb);
            *reinterpret_cast<float4*>(&sBl[row * LDK + seg]) = *reinterpret_cast<const float4*>(Blo + gb);
        }
        __syncthreads();

#pragma unroll
        for (int ks = 0; ks < 2; ks++) {
            const uint32_t kb = (uint32_t)(ks * 16 * 2);
            uint32_t ah[4][4], al[4][4], bh[4][2], bl[4][2];
#pragma unroll
            for (int mt = 0; mt < 4; mt++) {
                uint32_t r = (uint32_t)((wm * 64 + mt * 16) * LDK * 2) + aoff + kb;
                ldm_x4(ah[mt], uAh + r);
                ldm_x4(al[mt], uAl + r);
            }
#pragma unroll
            for (int nt = 0; nt < 4; nt++) {
                uint32_t r = (uint32_t)((wn * 32 + nt * 8) * LDK * 2) + boff + kb;
                ldm_x2(bh[nt], uBh + r);
                ldm_x2(bl[nt], uBl + r);
            }
#pragma unroll
            for (int mt = 0; mt < 4; mt++)
#pragma unroll
                for (int nt = 0; nt < 4; nt++) {
                    mma16816(acc[mt][nt], ah[mt], bh[nt]);
                    mma16816(acc[mt][nt], ah[mt], bl[nt]);
                    mma16816(acc[mt][nt], al[mt], bh[nt]);
                }
        }
    }

#pragma unroll
    for (int mt = 0; mt < 4; mt++) {
        int r0 = bm + wm * 64 + mt * 16 + (lane >> 2);
#pragma unroll
        for (int nt = 0; nt < 4; nt++) {
            int c0 = bn + wn * 32 + nt * 8 + (lane & 3) * 2;
            float bx = bias[c0], by = bias[c0 + 1];
            float2 o0 = make_float2(acc[mt][nt][0] + bx, acc[mt][nt][1] + by);
            float2 o1 = make_float2(acc[mt][nt][2] + bx, acc[mt][nt][3] + by);
            *reinterpret_cast<float2*>(Y + (size_t)r0 * N + c0) = o0;
            *reinterpret_cast<float2*>(Y + (size_t)(r0 + 8) * N + c0) = o1;
        }
    }
}

// =================================================================
// Flash attention on mma.sync, compacted keys, hi/lo 3-pass.
// Grid (LL/128, NH, BB), 256 threads = 8 warps, warp owns 16 q-rows.
// =================================================================
#define LDF 72
#define FQH 0
#define FQL 18432
#define FKH 36864
#define FKL 46080
#define FVH 55296
#define FVL 64512
#define FTOT 73728

__global__ __launch_bounds__(256)
void flash_mma(const __nv_bfloat16* __restrict__ Qhi, const __nv_bfloat16* __restrict__ Qlo,
               const __nv_bfloat16* __restrict__ Kchi, const __nv_bfloat16* __restrict__ Kclo,
               const __nv_bfloat16* __restrict__ Vthi, const __nv_bfloat16* __restrict__ Vtlo,
               const int* __restrict__ nact, float* __restrict__ Op)
{
    extern __shared__ char smem[];
    const int qt = blockIdx.x, h = blockIdx.y, b = blockIdx.z;
    const int tid = threadIdx.x, lane = tid & 31, w = tid >> 5;
    const int bh = b * NH + h;
    const int na = nact[b];
    const int ktiles = (na + 63) >> 6;
    const uint32_t su = smem_u32(smem);

    // load Q tile (128 rows x 64 dims, hi+lo)
    {
        const __nv_bfloat16* qh = Qhi + ((size_t)(b * LL + qt * 128)) * DM + h * HD;
        const __nv_bfloat16* ql = Qlo + ((size_t)(b * LL + qt * 128)) * DM + h * HD;
        for (int idx = tid; idx < 1024; idx += 256) {
            int row = idx >> 3, seg = idx & 7;
            *reinterpret_cast<float4*>(smem + FQH + row * 144 + seg * 16) =
                *reinterpret_cast<const float4*>(qh + (size_t)row * DM + seg * 8);
            *reinterpret_cast<float4*>(smem + FQL + row * 144 + seg * 16) =
                *reinterpret_cast<const float4*>(ql + (size_t)row * DM + seg * 8);
        }
    }

    float m0 = -3.0e38f, m1 = -3.0e38f, l0 = 0.f, l1 = 0.f;
    float oacc[8][4];
#pragma unroll
    for (int nt = 0; nt < 8; nt++)
#pragma unroll
        for (int e = 0; e < 4; e++) oacc[nt][e] = 0.f;

    const uint32_t aoff = (uint32_t)(((lane & 15) * LDF + (lane >> 4) * 8) * 2);
    const uint32_t boff = (uint32_t)(((lane & 7) * LDF + ((lane >> 3) & 1) * 8) * 2);
    const uint32_t qrowoff = (uint32_t)(w * 16 * 144);

    for (int kt = 0; kt < ktiles; kt++) {
        __syncthreads();
        // load K tile [64 keys][64 dims] and Vt tile [64 dims][64 keys]
        {
            const __nv_bfloat16* kh = Kchi + ((size_t)bh * LL + kt * 64) * HD;
            const __nv_bfloat16* kl = Kclo + ((size_t)bh * LL + kt * 64) * HD;
            const __nv_bfloat16* vh = Vthi + (size_t)bh * HD * LL + kt * 64;
            const __nv_bfloat16* vl = Vtlo + (size_t)bh * HD * LL + kt * 64;
            for (int idx = tid; idx < 512; idx += 256) {
                int row = idx >> 3, seg = idx & 7;
                *reinterpret_cast<float4*>(smem + FKH + row * 144 + seg * 16) =
                    *reinterpret_cast<const float4*>(kh + (size_t)row * HD + seg * 8);
                *reinterpret_cast<float4*>(smem + FKL + row * 144 + seg * 16) =
                    *reinterpret_cast<const float4*>(kl + (size_t)row * HD + seg * 8);
                *reinterpret_cast<float4*>(smem + FVH + row * 144 + seg * 16) =
                    *reinterpret_cast<const float4*>(vh + (size_t)row * LL + seg * 8);
                *reinterpret_cast<float4*>(smem + FVL + row * 144 + seg * 16) =
                    *reinterpret_cast<const float4*>(vl + (size_t)row * LL + seg * 8);
            }
        }
        __syncthreads();

        // ---- S = Q K^T : warp computes [16 x 64] ----
        float sacc[8][4];
#pragma unroll
        for (int nt = 0; nt < 8; nt++)
#pragma unroll
            for (int e = 0; e < 4; e++) sacc[nt][e] = 0.f;

#pragma unroll
        for (int ks = 0; ks < 4; ks++) {
            uint32_t ah[4], al[4];
            ldm_x4(ah, su + FQH + qrowoff + aoff + ks * 32);
            ldm_x4(al, su + FQL + qrowoff + aoff + ks * 32);
#pragma unroll
            for (int nt = 0; nt < 8; nt++) {
                uint32_t bh2[2], bl2[2];
                ldm_x2(bh2, su + FKH + nt * 1152 + boff + ks * 32);
                ldm_x2(bl2, su + FKL + nt * 1152 + boff + ks * 32);
                mma16816(sacc[nt], ah, bh2);
                mma16816(sacc[nt], ah, bl2);
                mma16816(sacc[nt], al, bh2);
            }
        }

        // ---- pad mask (last tile only) ----
        if (kt == ktiles - 1) {
            int jb = kt * 64 + 2 * (lane & 3);
#pragma unroll
            for (int nt = 0; nt < 8; nt++) {
                if (jb + nt * 8     >= na) { sacc[nt][0] = -1e30f; sacc[nt][2] = -1e30f; }
                if (jb + nt * 8 + 1 >= na) { sacc[nt][1] = -1e30f; sacc[nt][3] = -1e30f; }
            }
        }

        // ---- online softmax (base-2; scale folded into Q) ----
        float rm0 = -3.0e38f, rm1 = -3.0e38f;
#pragma unroll
        for (int nt = 0; nt < 8; nt++) {
            rm0 = fmaxf(rm0, fmaxf(sacc[nt][0], sacc[nt][1]));
            rm1 = fmaxf(rm1, fmaxf(sacc[nt][2], sacc[nt][3]));
        }
        rm0 = fmaxf(rm0, __shfl_xor_sync(0xffffffffu, rm0, 1));
        rm0 = fmaxf(rm0, __shfl_xor_sync(0xffffffffu, rm0, 2));
        rm1 = fmaxf(rm1, __shfl_xor_sync(0xffffffffu, rm1, 1));
        rm1 = fmaxf(rm1, __shfl_xor_sync(0xffffffffu, rm1, 2));
        float mn0 = fmaxf(m0, rm0), mn1 = fmaxf(m1, rm1);
        float c0 = ex2(m0 - mn0), c1 = ex2(m1 - mn1);
        m0 = mn0; m1 = mn1;

        float rs0 = 0.f, rs1 = 0.f;
        uint32_t pah[4][4], pal[4][4];
#pragma unroll
        for (int t = 0; t < 4; t++) {
#pragma unroll
            for (int e = 0; e < 2; e++) {
                int nt = 2 * t + e;
                float p0 = ex2(sacc[nt][0] - mn0);
                float p1 = ex2(sacc[nt][1] - mn0);
                float p2 = ex2(sacc[nt][2] - mn1);
                float p3 = ex2(sacc[nt][3] - mn1);
                rs0 += p0 + p1;
                rs1 += p2 + p3;
                __nv_bfloat16 h0 = __float2bfloat16(p0), h1 = __float2bfloat16(p1);
                __nv_bfloat16 h2 = __float2bfloat16(p2), h3 = __float2bfloat16(p3);
                pah[t][2 * e]     = pack2(h0, h1);
                pah[t][2 * e + 1] = pack2(h2, h3);
                __nv_bfloat16 r0b = __float2bfloat16(p0 - __bfloat162float(h0));
                __nv_bfloat16 r1b = __float2bfloat16(p1 - __bfloat162float(h1));
                __nv_bfloat16 r2b = __float2bfloat16(p2 - __bfloat162float(h2));
                __nv_bfloat16 r3b = __float2bfloat16(p3 - __bfloat162float(h3));
                pal[t][2 * e]     = pack2(r0b, r1b);
                pal[t][2 * e + 1] = pack2(r2b, r3b);
            }
        }
        // quad-reduce the row sums (THE R5 BUG: each lane only sees 16/64 cols)
        rs0 += __shfl_xor_sync(0xffffffffu, rs0, 1);
        rs0 += __shfl_xor_sync(0xffffffffu, rs0, 2);
        rs1 += __shfl_xor_sync(0xffffffffu, rs1, 1);
        rs1 += __shfl_xor_sync(0xffffffffu, rs1, 2);
        l0 = l0 * c0 + rs0;
        l1 = l1 * c1 + rs1;
#pragma unroll
        for (int nt = 0; nt < 8; nt++) {
            oacc[nt][0] *= c0; oacc[nt][1] *= c0;
            oacc[nt][2] *= c1; oacc[nt][3] *= c1;
        }

        // ---- O += P V ----
#pragma unroll
        for (int t = 0; t < 4; t++) {
#pragma unroll
            for (int nt = 0; nt < 8; nt++) {
                uint32_t bvh[2], bvl[2];
                ldm_x2(bvh, su + FVH + nt * 1152 + boff + t * 32);
                ldm_x2(bvl, su + FVL + nt * 1152 + boff + t * 32);
                mma16816(oacc[nt], pah[t], bvh);
                mma16816(oacc[nt], pah[t], bvl);
                mma16816(oacc[nt], pal[t], bvh);
            }
        }
    }

    // ---- normalize + write ----
    float i0 = 1.f / l0, i1 = 1.f / l1;
    int r = lane >> 2;
    size_t row0 = (size_t)b * LL + qt * 128 + w * 16 + r;
    int cc0 = h * HD + 2 * (lane & 3);
#pragma unroll
    for (int nt = 0; nt < 8; nt++) {
        int cc = cc0 + nt * 8;
        *reinterpret_cast<float2*>(Op + row0 * DM + cc) =
            make_float2(oacc[nt][0] * i0, oacc[nt][1] * i0);
        *reinterpret_cast<float2*>(Op + (row0 + 8) * DM + cc) =
            make_float2(oacc[nt][2] * i1, oacc[nt][3] * i1);
    }
}

// =================================================================
// launch
// =================================================================
extern "C" void kernel_launch(void* const* d_in, const int* in_sizes, int n_in,
                              void* d_out, int out_size)
{
    const float* q    = (const float*)d_in[0];
    const float* k    = (const float*)d_in[1];
    const float* v    = (const float*)d_in[2];
    const int*   mask = (const int*)d_in[3];
    const float* Wq   = (const float*)d_in[4];
    const float* bq   = (const float*)d_in[5];
    const float* Wk   = (const float*)d_in[6];
    const float* bk   = (const float*)d_in[7];
    const float* Wv   = (const float*)d_in[8];
    const float* bv   = (const float*)d_in[9];
    const float* Wo   = (const float*)d_in[10];
    const float* bo   = (const float*)d_in[11];

    float *gq, *gk, *gv, *ga;
    __nv_bfloat16 *xhi, *xlo, *whi, *wlo, *qhi, *qlo, *kchi, *kclo, *vthi, *vtlo;
    int *cidx, *nact;
    cudaGetSymbolAddress((void**)&gq, g_qp);
    cudaGetSymbolAddress((void**)&gk, g_kp);
    cudaGetSymbolAddress((void**)&gv, g_vp);
    cudaGetSymbolAddress((void**)&ga, g_at);
    cudaGetSymbolAddress((void**)&xhi, g_xhi);
    cudaGetSymbolAddress((void**)&xlo, g_xlo);
    cudaGetSymbolAddress((void**)&whi, g_whi);
    cudaGetSymbolAddress((void**)&wlo, g_wlo);
    cudaGetSymbolAddress((void**)&qhi, g_qhi);
    cudaGetSymbolAddress((void**)&qlo, g_qlo);
    cudaGetSymbolAddress((void**)&kchi, g_kchi);
    cudaGetSymbolAddress((void**)&kclo, g_kclo);
    cudaGetSymbolAddress((void**)&vthi, g_vthi);
    cudaGetSymbolAddress((void**)&vtlo, g_vtlo);
    cudaGetSymbolAddress((void**)&cidx, g_cidx);
    cudaGetSymbolAddress((void**)&nact, g_nact);

    cudaFuncSetAttribute(flash_mma, cudaFuncAttributeMaxDynamicSharedMemorySize, FTOT);

    const int NX = ML * DM;
    const int NW = DM * DM;
    dim3 gg(DM / 128, ML / 128);

    compact_mask<<<BB, 256>>>(mask, cidx, nact);

    // projections
    split_bf16<<<NX / 1024, 256>>>(q, xhi, xlo, NX);
    split_bf16<<<NW / 1024, 256>>>(Wq, whi, wlo, NW);
    gemm_mma<<<gg, 256>>>(xhi, xlo, whi, wlo, bq, gq, ML, DM, DM);

    split_bf16<<<NX / 1024, 256>>>(k, xhi, xlo, NX);
    split_bf16<<<NW / 1024, 256>>>(Wk, whi, wlo, NW);
    gemm_mma<<<gg, 256>>>(xhi, xlo, whi, wlo, bk, gk, ML, DM, DM);

    split_bf16<<<NX / 1024, 256>>>(v, xhi, xlo, NX);
    split_bf16<<<NW / 1024, 256>>>(Wv, whi, wlo, NW);
    gemm_mma<<<gg, 256>>>(xhi, xlo, whi, wlo, bv, gv, ML, DM, DM);

    // flash preprocessing: scaled Q split (0.125 * log2(e)), K/V gather+split
    split_bf16_scaled<<<NX / 1024, 256>>>(gq, qhi, qlo, NX, 0.18033688011112042f);
    gather_kv<<<dim3(LL / 128, NH, BB), 256>>>(gk, gv, cidx, nact, kchi, kclo, vthi, vtlo);

    // attention
    flash_mma<<<dim3(LL / 128, NH, BB), 256, FTOT>>>(qhi, qlo, kchi, kclo, vthi, vtlo,
                                                     nact, ga);

    // output projection
    split_bf16<<<NX / 1024, 256>>>(ga, xhi, xlo, NX);
    split_bf16<<<NW / 1024, 256>>>(Wo, whi, wlo, NW);
    gemm_mma<<<gg, 256>>>(xhi, xlo, whi, wlo, bo, (float*)d_out, ML, DM, DM);
}

// round 8
// speedup vs baseline: 3.9478x; 1.1640x over previous
#include <cuda_runtime.h>
#include <cuda_bf16.h>
#include <cstdint>

#define DM 1024
#define NH 16
#define HD 64
#define BB 2
#define LL 2048
#define ML (BB * LL)  // 4096 total rows

// ---------------- scratch (no allocation allowed) ----------------
__device__ float g_kp[ML * DM];
__device__ float g_vp[ML * DM];
__device__ __nv_bfloat16 g_x0hi[ML * DM], g_x0lo[ML * DM];
__device__ __nv_bfloat16 g_x1hi[ML * DM], g_x1lo[ML * DM];
__device__ __nv_bfloat16 g_x2hi[ML * DM], g_x2lo[ML * DM];
__device__ __nv_bfloat16 g_w0hi[DM * DM], g_w0lo[DM * DM];
__device__ __nv_bfloat16 g_w1hi[DM * DM], g_w1lo[DM * DM];
__device__ __nv_bfloat16 g_w2hi[DM * DM], g_w2lo[DM * DM];
__device__ __nv_bfloat16 g_qhi[ML * DM], g_qlo[ML * DM];
__device__ __nv_bfloat16 g_kchi[BB * NH * LL * HD], g_kclo[BB * NH * LL * HD];
__device__ __nv_bfloat16 g_vthi[BB * NH * HD * LL], g_vtlo[BB * NH * HD * LL];
__device__ __nv_bfloat16 g_ahi[ML * DM], g_alo[ML * DM];  // flash output (split)
__device__ int g_cidx[BB * LL];
__device__ int g_nact[BB];

// ================= helpers (base compute_103 PTX only) ==========
__device__ __forceinline__ uint32_t smem_u32(const void* p) {
    uint32_t a;
    asm("{ .reg .u64 t; cvta.to.shared.u64 t, %1; cvt.u32.u64 %0, t; }" : "=r"(a) : "l"(p));
    return a;
}
__device__ __forceinline__ void ldm_x4(uint32_t* r, uint32_t addr) {
    asm volatile("ldmatrix.sync.aligned.m8n8.x4.shared.b16 {%0,%1,%2,%3}, [%4];"
                 : "=r"(r[0]), "=r"(r[1]), "=r"(r[2]), "=r"(r[3]) : "r"(addr));
}
__device__ __forceinline__ void ldm_x2(uint32_t* r, uint32_t addr) {
    asm volatile("ldmatrix.sync.aligned.m8n8.x2.shared.b16 {%0,%1}, [%2];"
                 : "=r"(r[0]), "=r"(r[1]) : "r"(addr));
}
__device__ __forceinline__ void mma16816(float* c, const uint32_t* a, const uint32_t* b) {
    asm volatile("mma.sync.aligned.m16n8k16.row.col.f32.bf16.bf16.f32 "
                 "{%0,%1,%2,%3}, {%4,%5,%6,%7}, {%8,%9}, {%0,%1,%2,%3};"
                 : "+f"(c[0]), "+f"(c[1]), "+f"(c[2]), "+f"(c[3])
                 : "r"(a[0]), "r"(a[1]), "r"(a[2]), "r"(a[3]), "r"(b[0]), "r"(b[1]));
}
__device__ __forceinline__ float ex2(float x) {
    float y;
    asm("ex2.approx.ftz.f32 %0, %1;" : "=f"(y) : "f"(x));
    return y;
}
__device__ __forceinline__ uint32_t pack2(__nv_bfloat16 a, __nv_bfloat16 b) {
    __nv_bfloat162 t = __halves2bfloat162(a, b);
    return *reinterpret_cast<uint32_t*>(&t);
}
#define CP16(d, s) asm volatile("cp.async.cg.shared.global [%0], [%1], 16;" :: "r"(d), "l"(s))
#define CPCOMMIT() asm volatile("cp.async.commit_group;" ::: "memory")
#define CPWAIT0()  asm volatile("cp.async.wait_group 0;" ::: "memory")

// =================================================================
// split fp32 -> bf16 hi/lo
// =================================================================
__global__ __launch_bounds__(256)
void split_bf16(const float* __restrict__ x, __nv_bfloat16* __restrict__ hi,
                __nv_bfloat16* __restrict__ lo, int n)
{
    int i = (blockIdx.x * 256 + threadIdx.x) * 4;
    if (i >= n) return;
    float4 f = *reinterpret_cast<const float4*>(x + i);
    __nv_bfloat16 h0 = __float2bfloat16(f.x);
    __nv_bfloat16 h1 = __float2bfloat16(f.y);
    __nv_bfloat16 h2 = __float2bfloat16(f.z);
    __nv_bfloat16 h3 = __float2bfloat16(f.w);
    *reinterpret_cast<__nv_bfloat162*>(hi + i)     = __nv_bfloat162(h0, h1);
    *reinterpret_cast<__nv_bfloat162*>(hi + i + 2) = __nv_bfloat162(h2, h3);
    *reinterpret_cast<__nv_bfloat162*>(lo + i) = __nv_bfloat162(
        __float2bfloat16(f.x - __bfloat162float(h0)),
        __float2bfloat16(f.y - __bfloat162float(h1)));
    *reinterpret_cast<__nv_bfloat162*>(lo + i + 2) = __nv_bfloat162(
        __float2bfloat16(f.z - __bfloat162float(h2)),
        __float2bfloat16(f.w - __bfloat162float(h3)));
}

// =================================================================
// mask compaction (deterministic)
// =================================================================
__global__ __launch_bounds__(256)
void compact_mask(const int* __restrict__ mask, int* __restrict__ cidx,
                  int* __restrict__ nact)
{
    int b = blockIdx.x, tid = threadIdx.x;
    __shared__ int ws[256];
    const int* mb = mask + b * LL;
    int base = tid * 8;
    int loc[8];
    int cnt = 0;
#pragma unroll
    for (int i = 0; i < 8; i++) { loc[i] = cnt; cnt += (mb[base + i] == 0); }
    ws[tid] = cnt;
    __syncthreads();
    if (tid == 0) {
        int acc = 0;
        for (int i = 0; i < 256; i++) { int t = ws[i]; ws[i] = acc; acc += t; }
        nact[b] = acc;
    }
    __syncthreads();
    int off = ws[tid];
#pragma unroll
    for (int i = 0; i < 8; i++)
        if (mb[base + i] == 0) cidx[b * LL + off + loc[i]] = base + i;
}

// =================================================================
// gather compacted K (hi/lo) and transposed V (hi/lo)
// =================================================================
__global__ __launch_bounds__(256)
void gather_kv(const float* __restrict__ Kp, const float* __restrict__ Vp,
               const int* __restrict__ cidx, const int* __restrict__ nact,
               __nv_bfloat16* __restrict__ Kchi, __nv_bfloat16* __restrict__ Kclo,
               __nv_bfloat16* __restrict__ Vthi, __nv_bfloat16* __restrict__ Vtlo)
{
    __shared__ float sv[128][65];
    const int it = blockIdx.x, h = blockIdx.y, b = blockIdx.z;
    const int bh = b * NH + h;
    const int na = nact[b];
    const int bound = (na + 63) & ~63;
    const int i0 = it * 128;
    if (i0 >= bound) return;
    const int tid = threadIdx.x;

#pragma unroll
    for (int t = 0; t < 32; t++) {
        int idx = tid + t * 256;
        int d = idx & 63, il = idx >> 6;
        int gi = i0 + il;
        float kv = 0.f, vv = 0.f;
        if (gi < na) {
            int src = cidx[b * LL + gi];
            size_t g = ((size_t)(b * LL) + src) * DM + h * HD + d;
            kv = Kp[g];
            vv = Vp[g];
        }
        __nv_bfloat16 kh = __float2bfloat16(kv);
        size_t ko = ((size_t)bh * LL + gi) * HD + d;
        Kchi[ko] = kh;
        Kclo[ko] = __float2bfloat16(kv - __bfloat162float(kh));
        sv[il][d] = vv;
    }
    __syncthreads();
#pragma unroll
    for (int t = 0; t < 32; t++) {
        int idx = tid + t * 256;
        int ii = idx & 127, d = idx >> 7;
        float v = sv[ii][d];
        __nv_bfloat16 vh = __float2bfloat16(v);
        size_t o = ((size_t)bh * HD + d) * LL + i0 + ii;
        Vthi[o] = vh;
        Vtlo[o] = __float2bfloat16(v - __bfloat162float(vh));
    }
}

// =================================================================
// cp.async double-buffered GEMM, batched over z.
// =================================================================
#define LDK 40
#define GSTG 40960

struct GP {
    const __nv_bfloat16 *Ahi[3], *Alo[3], *Bhi[3], *Blo[3];
    const float* bias[3];
    float* Yf[3];
    __nv_bfloat16 *Yhi[3], *Ylo[3];
    float scale[3];
    int mode[3];
};

__global__ __launch_bounds__(256)
void gemm_mma2(GP p)
{
    extern __shared__ char smem[];
    const int z = blockIdx.z;
    const __nv_bfloat16* __restrict__ Ahi = p.Ahi[z];
    const __nv_bfloat16* __restrict__ Alo = p.Alo[z];
    const __nv_bfloat16* __restrict__ Bhi = p.Bhi[z];
    const __nv_bfloat16* __restrict__ Blo = p.Blo[z];
    const float* __restrict__ bias = p.bias[z];

    const int tid = threadIdx.x, lane = tid & 31, wid = tid >> 5;
    const int wm = wid & 1, wn = wid >> 1;
    const int bm = blockIdx.y * 128, bn = blockIdx.x * 128;
    const uint32_t su = smem_u32(smem);

    float acc[4][4][4];
#pragma unroll
    for (int mt = 0; mt < 4; mt++)
#pragma unroll
        for (int nt = 0; nt < 4; nt++)
#pragma unroll
            for (int e = 0; e < 4; e++) acc[mt][nt][e] = 0.f;

    const uint32_t aoff = (uint32_t)(((lane & 15) * LDK + (lane >> 4) * 8) * 2);
    const uint32_t boff = (uint32_t)(((lane & 7) * LDK + ((lane >> 3) & 1) * 8) * 2);

    auto issue = [&](int s, int c) {
        uint32_t sb = su + (uint32_t)s * GSTG;
        int k0 = c * 32;
#pragma unroll
        for (int rep = 0; rep < 2; rep++) {
            int ch = tid + rep * 256;              // 0..511: 128 rows x 4 segs (64B/row)
            int row = ch >> 2, seg = ch & 3;
            uint32_t doff = (uint32_t)(row * 80 + seg * 16);
            size_t goA = (size_t)(bm + row) * DM + k0 + seg * 8;
            size_t goB = (size_t)(bn + row) * DM + k0 + seg * 8;
            CP16(sb + doff,         Ahi + goA);
            CP16(sb + 10240 + doff, Alo + goA);
            CP16(sb + 20480 + doff, Bhi + goB);
            CP16(sb + 30720 + doff, Blo + goB);
        }
    };

    issue(0, 0);
    CPCOMMIT();

    for (int c = 0; c < 32; c++) {
        CPWAIT0();
        __syncthreads();
        if (c + 1 < 32) { issue((c + 1) & 1, c + 1); CPCOMMIT(); }
        const uint32_t sb = su + (uint32_t)(c & 1) * GSTG;
        const uint32_t uAh = sb, uAl = sb + 10240, uBh = sb + 20480, uBl = sb + 30720;
#pragma unroll
        for (int ks = 0; ks < 2; ks++) {
            const uint32_t kb = (uint32_t)(ks * 32);
            uint32_t ah[4][4], al[4][4], bh[4][2], bl[4][2];
#pragma unroll
            for (int mt = 0; mt < 4; mt++) {
                uint32_t r = (uint32_t)((wm * 64 + mt * 16) * LDK * 2) + aoff + kb;
                ldm_x4(ah[mt], uAh + r);
                ldm_x4(al[mt], uAl + r);
            }
#pragma unroll
            for (int nt = 0; nt < 4; nt++) {
                uint32_t r = (uint32_t)((wn * 32 + nt * 8) * LDK * 2) + boff + kb;
                ldm_x2(bh[nt], uBh + r);
                ldm_x2(bl[nt], uBl + r);
            }
#pragma unroll
            for (int mt = 0; mt < 4; mt++)
#pragma unroll
                for (int nt = 0; nt < 4; nt++) {
                    mma16816(acc[mt][nt], ah[mt], bh[nt]);
                    mma16816(acc[mt][nt], ah[mt], bl[nt]);
                    mma16816(acc[mt][nt], al[mt], bh[nt]);
                }
        }
    }

    if (p.mode[z] == 0) {
        float* Y = p.Yf[z];
#pragma unroll
        for (int mt = 0; mt < 4; mt++) {
            int r0 = bm + wm * 64 + mt * 16 + (lane >> 2);
#pragma unroll
            for (int nt = 0; nt < 4; nt++) {
                int c0 = bn + wn * 32 + nt * 8 + (lane & 3) * 2;
                float bx = bias[c0], by = bias[c0 + 1];
                *reinterpret_cast<float2*>(Y + (size_t)r0 * DM + c0) =
                    make_float2(acc[mt][nt][0] + bx, acc[mt][nt][1] + by);
                *reinterpret_cast<float2*>(Y + (size_t)(r0 + 8) * DM + c0) =
                    make_float2(acc[mt][nt][2] + bx, acc[mt][nt][3] + by);
            }
        }
    } else {
        __nv_bfloat16* Yh = p.Yhi[z];
        __nv_bfloat16* Yl = p.Ylo[z];
        const float sc = p.scale[z];
#pragma unroll
        for (int mt = 0; mt < 4; mt++) {
            int r0 = bm + wm * 64 + mt * 16 + (lane >> 2);
#pragma unroll
            for (int nt = 0; nt < 4; nt++) {
                int c0 = bn + wn * 32 + nt * 8 + (lane & 3) * 2;
                float bx = bias[c0], by = bias[c0 + 1];
                float y0 = (acc[mt][nt][0] + bx) * sc;
                float y1 = (acc[mt][nt][1] + by) * sc;
                float y2 = (acc[mt][nt][2] + bx) * sc;
                float y3 = (acc[mt][nt][3] + by) * sc;
                __nv_bfloat16 h0 = __float2bfloat16(y0), h1 = __float2bfloat16(y1);
                __nv_bfloat16 h2 = __float2bfloat16(y2), h3 = __float2bfloat16(y3);
                *reinterpret_cast<uint32_t*>(Yh + (size_t)r0 * DM + c0) = pack2(h0, h1);
                *reinterpret_cast<uint32_t*>(Yh + (size_t)(r0 + 8) * DM + c0) = pack2(h2, h3);
                *reinterpret_cast<uint32_t*>(Yl + (size_t)r0 * DM + c0) =
                    pack2(__float2bfloat16(y0 - __bfloat162float(h0)),
                          __float2bfloat16(y1 - __bfloat162float(h1)));
                *reinterpret_cast<uint32_t*>(Yl + (size_t)(r0 + 8) * DM + c0) =
                    pack2(__float2bfloat16(y2 - __bfloat162float(h2)),
                          __float2bfloat16(y3 - __bfloat162float(h3)));
            }
        }
    }
}

// =================================================================
// Flash attention, mma.sync + cp.async double-buffered K/V tiles.
// =================================================================
#define FQH 0
#define FQL 18432
#define FSB 36864
#define FSTG 36864
#define FTOT (FSB + 2 * FSTG)  // 110592

__global__ __launch_bounds__(256)
void flash_mma(const __nv_bfloat16* __restrict__ Qhi, const __nv_bfloat16* __restrict__ Qlo,
               const __nv_bfloat16* __restrict__ Kchi, const __nv_bfloat16* __restrict__ Kclo,
               const __nv_bfloat16* __restrict__ Vthi, const __nv_bfloat16* __restrict__ Vtlo,
               const int* __restrict__ nact,
               __nv_bfloat16* __restrict__ Ohi, __nv_bfloat16* __restrict__ Olo)
{
    extern __shared__ char smem[];
    const int qt = blockIdx.x, h = blockIdx.y, b = blockIdx.z;
    const int tid = threadIdx.x, lane = tid & 31, w = tid >> 5;
    const int bh = b * NH + h;
    const int na = nact[b];
    const int ktiles = (na + 63) >> 6;
    const uint32_t su = smem_u32(smem);

    {
        const __nv_bfloat16* qh = Qhi + ((size_t)(b * LL + qt * 128)) * DM + h * HD;
        const __nv_bfloat16* ql = Qlo + ((size_t)(b * LL + qt * 128)) * DM + h * HD;
        for (int idx = tid; idx < 1024; idx += 256) {
            int row = idx >> 3, seg = idx & 7;
            *reinterpret_cast<float4*>(smem + FQH + row * 144 + seg * 16) =
                *reinterpret_cast<const float4*>(qh + (size_t)row * DM + seg * 8);
            *reinterpret_cast<float4*>(smem + FQL + row * 144 + seg * 16) =
                *reinterpret_cast<const float4*>(ql + (size_t)row * DM + seg * 8);
        }
    }

    // THE R7 BUG: previous issue() covered only 64B of each 128B row.
    // 512 chunks = 64 rows x 8 segs of 16B; 2 reps over 256 threads.
    auto issue = [&](int s, int kt) {
        uint32_t sb = su + FSB + (uint32_t)s * FSTG;
        const __nv_bfloat16* kh = Kchi + ((size_t)bh * LL + kt * 64) * HD;
        const __nv_bfloat16* kl = Kclo + ((size_t)bh * LL + kt * 64) * HD;
        const __nv_bfloat16* vh = Vthi + (size_t)bh * HD * LL + kt * 64;
        const __nv_bfloat16* vl = Vtlo + (size_t)bh * HD * LL + kt * 64;
#pragma unroll
        for (int rep = 0; rep < 2; rep++) {
            int ch = tid + rep * 256;
            int row = ch >> 3, seg = ch & 7;
            uint32_t doff = (uint32_t)(row * 144 + seg * 16);
            CP16(sb + doff,          kh + (size_t)row * HD + seg * 8);
            CP16(sb + 9216 + doff,   kl + (size_t)row * HD + seg * 8);
            CP16(sb + 18432 + doff,  vh + (size_t)row * LL + seg * 8);
            CP16(sb + 27648 + doff,  vl + (size_t)row * LL + seg * 8);
        }
    };

    float m0 = -3.0e38f, m1 = -3.0e38f, l0 = 0.f, l1 = 0.f;
    float oacc[8][4];
#pragma unroll
    for (int nt = 0; nt < 8; nt++)
#pragma unroll
        for (int e = 0; e < 4; e++) oacc[nt][e] = 0.f;

    const uint32_t qaoff = (uint32_t)(((lane & 15) * 72 + (lane >> 4) * 8) * 2);
    const uint32_t boff  = (uint32_t)(((lane & 7) * 72 + ((lane >> 3) & 1) * 8) * 2);
    const uint32_t qrowoff = (uint32_t)(w * 16 * 144);

    issue(0, 0);
    CPCOMMIT();

    for (int kt = 0; kt < ktiles; kt++) {
        CPWAIT0();
        __syncthreads();
        if (kt + 1 < ktiles) { issue((kt + 1) & 1, kt + 1); CPCOMMIT(); }
        const uint32_t sb = su + FSB + (uint32_t)(kt & 1) * FSTG;
        const uint32_t uKH = sb, uKL = sb + 9216, uVH = sb + 18432, uVL = sb + 27648;

        float sacc[8][4];
#pragma unroll
        for (int nt = 0; nt < 8; nt++)
#pragma unroll
            for (int e = 0; e < 4; e++) sacc[nt][e] = 0.f;

#pragma unroll
        for (int ks = 0; ks < 4; ks++) {
            uint32_t ah[4], al[4];
            ldm_x4(ah, su + FQH + qrowoff + qaoff + ks * 32);
            ldm_x4(al, su + FQL + qrowoff + qaoff + ks * 32);
#pragma unroll
            for (int nt = 0; nt < 8; nt++) {
                uint32_t bh2[2], bl2[2];
                ldm_x2(bh2, uKH + nt * 1152 + boff + ks * 32);
                ldm_x2(bl2, uKL + nt * 1152 + boff + ks * 32);
                mma16816(sacc[nt], ah, bh2);
                mma16816(sacc[nt], ah, bl2);
                mma16816(sacc[nt], al, bh2);
            }
        }

        if (kt == ktiles - 1) {
            int jb = kt * 64 + 2 * (lane & 3);
#pragma unroll
            for (int nt = 0; nt < 8; nt++) {
                if (jb + nt * 8     >= na) { sacc[nt][0] = -1e30f; sacc[nt][2] = -1e30f; }
                if (jb + nt * 8 + 1 >= na) { sacc[nt][1] = -1e30f; sacc[nt][3] = -1e30f; }
            }
        }

        float rm0 = -3.0e38f, rm1 = -3.0e38f;
#pragma unroll
        for (int nt = 0; nt < 8; nt++) {
            rm0 = fmaxf(rm0, fmaxf(sacc[nt][0], sacc[nt][1]));
            rm1 = fmaxf(rm1, fmaxf(sacc[nt][2], sacc[nt][3]));
        }
        rm0 = fmaxf(rm0, __shfl_xor_sync(0xffffffffu, rm0, 1));
        rm0 = fmaxf(rm0, __shfl_xor_sync(0xffffffffu, rm0, 2));
        rm1 = fmaxf(rm1, __shfl_xor_sync(0xffffffffu, rm1, 1));
        rm1 = fmaxf(rm1, __shfl_xor_sync(0xffffffffu, rm1, 2));
        float mn0 = fmaxf(m0, rm0), mn1 = fmaxf(m1, rm1);
        float c0 = ex2(m0 - mn0), c1 = ex2(m1 - mn1);
        m0 = mn0; m1 = mn1;

        float rs0 = 0.f, rs1 = 0.f;
        uint32_t pah[4][4], pal[4][4];
#pragma unroll
        for (int t = 0; t < 4; t++) {
#pragma unroll
            for (int e = 0; e < 2; e++) {
                int nt = 2 * t + e;
                float p0 = ex2(sacc[nt][0] - mn0);
                float p1 = ex2(sacc[nt][1] - mn0);
                float p2 = ex2(sacc[nt][2] - mn1);
                float p3 = ex2(sacc[nt][3] - mn1);
                rs0 += p0 + p1;
                rs1 += p2 + p3;
                __nv_bfloat16 h0 = __float2bfloat16(p0), h1 = __float2bfloat16(p1);
                __nv_bfloat16 h2 = __float2bfloat16(p2), h3 = __float2bfloat16(p3);
                pah[t][2 * e]     = pack2(h0, h1);
                pah[t][2 * e + 1] = pack2(h2, h3);
                pal[t][2 * e]     = pack2(__float2bfloat16(p0 - __bfloat162float(h0)),
                                          __float2bfloat16(p1 - __bfloat162float(h1)));
                pal[t][2 * e + 1] = pack2(__float2bfloat16(p2 - __bfloat162float(h2)),
                                          __float2bfloat16(p3 - __bfloat162float(h3)));
            }
        }
        rs0 += __shfl_xor_sync(0xffffffffu, rs0, 1);
        rs0 += __shfl_xor_sync(0xffffffffu, rs0, 2);
        rs1 += __shfl_xor_sync(0xffffffffu, rs1, 1);
        rs1 += __shfl_xor_sync(0xffffffffu, rs1, 2);
        l0 = l0 * c0 + rs0;
        l1 = l1 * c1 + rs1;
#pragma unroll
        for (int nt = 0; nt < 8; nt++) {
            oacc[nt][0] *= c0; oacc[nt][1] *= c0;
            oacc[nt][2] *= c1; oacc[nt][3] *= c1;
        }

#pragma unroll
        for (int t = 0; t < 4; t++) {
#pragma unroll
            for (int nt = 0; nt < 8; nt++) {
                uint32_t bvh[2], bvl[2];
                ldm_x2(bvh, uVH + nt * 1152 + boff + t * 32);
                ldm_x2(bvl, uVL + nt * 1152 + boff + t * 32);
                mma16816(oacc[nt], pah[t], bvh);
                mma16816(oacc[nt], pah[t], bvl);
                mma16816(oacc[nt], pal[t], bvh);
            }
        }
    }

    float i0 = 1.f / l0, i1 = 1.f / l1;
    int r = lane >> 2;
    size_t row0 = (size_t)b * LL + qt * 128 + w * 16 + r;
    int cc0 = h * HD + 2 * (lane & 3);
#pragma unroll
    for (int nt = 0; nt < 8; nt++) {
        int cc = cc0 + nt * 8;
        float y0 = oacc[nt][0] * i0, y1 = oacc[nt][1] * i0;
        float y2 = oacc[nt][2] * i1, y3 = oacc[nt][3] * i1;
        __nv_bfloat16 h0 = __float2bfloat16(y0), h1 = __float2bfloat16(y1);
        __nv_bfloat16 h2 = __float2bfloat16(y2), h3 = __float2bfloat16(y3);
        *reinterpret_cast<uint32_t*>(Ohi + row0 * DM + cc) = pack2(h0, h1);
        *reinterpret_cast<uint32_t*>(Ohi + (row0 + 8) * DM + cc) = pack2(h2, h3);
        *reinterpret_cast<uint32_t*>(Olo + row0 * DM + cc) =
            pack2(__float2bfloat16(y0 - __bfloat162float(h0)),
                  __float2bfloat16(y1 - __bfloat162float(h1)));
        *reinterpret_cast<uint32_t*>(Olo + (row0 + 8) * DM + cc) =
            pack2(__float2bfloat16(y2 - __bfloat162float(h2)),
                  __float2bfloat16(y3 - __bfloat162float(h3)));
    }
}

// =================================================================
// launch
// =================================================================
extern "C" void kernel_launch(void* const* d_in, const int* in_sizes, int n_in,
                              void* d_out, int out_size)
{
    const float* q    = (const float*)d_in[0];
    const float* k    = (const float*)d_in[1];
    const float* v    = (const float*)d_in[2];
    const int*   mask = (const int*)d_in[3];
    const float* Wq   = (const float*)d_in[4];
    const float* bq   = (const float*)d_in[5];
    const float* Wk   = (const float*)d_in[6];
    const float* bk   = (const float*)d_in[7];
    const float* Wv   = (const float*)d_in[8];
    const float* bv   = (const float*)d_in[9];
    const float* Wo   = (const float*)d_in[10];
    const float* bo   = (const float*)d_in[11];

    float *gk, *gv;
    __nv_bfloat16 *x0h, *x0l, *x1h, *x1l, *x2h, *x2l;
    __nv_bfloat16 *w0h, *w0l, *w1h, *w1l, *w2h, *w2l;
    __nv_bfloat16 *qhi, *qlo, *kchi, *kclo, *vthi, *vtlo, *ahi, *alo;
    int *cidx, *nact;
    cudaGetSymbolAddress((void**)&gk, g_kp);
    cudaGetSymbolAddress((void**)&gv, g_vp);
    cudaGetSymbolAddress((void**)&x0h, g_x0hi); cudaGetSymbolAddress((void**)&x0l, g_x0lo);
    cudaGetSymbolAddress((void**)&x1h, g_x1hi); cudaGetSymbolAddress((void**)&x1l, g_x1lo);
    cudaGetSymbolAddress((void**)&x2h, g_x2hi); cudaGetSymbolAddress((void**)&x2l, g_x2lo);
    cudaGetSymbolAddress((void**)&w0h, g_w0hi); cudaGetSymbolAddress((void**)&w0l, g_w0lo);
    cudaGetSymbolAddress((void**)&w1h, g_w1hi); cudaGetSymbolAddress((void**)&w1l, g_w1lo);
    cudaGetSymbolAddress((void**)&w2h, g_w2hi); cudaGetSymbolAddress((void**)&w2l, g_w2lo);
    cudaGetSymbolAddress((void**)&qhi, g_qhi);  cudaGetSymbolAddress((void**)&qlo, g_qlo);
    cudaGetSymbolAddress((void**)&kchi, g_kchi); cudaGetSymbolAddress((void**)&kclo, g_kclo);
    cudaGetSymbolAddress((void**)&vthi, g_vthi); cudaGetSymbolAddress((void**)&vtlo, g_vtlo);
    cudaGetSymbolAddress((void**)&ahi, g_ahi);  cudaGetSymbolAddress((void**)&alo, g_alo);
    cudaGetSymbolAddress((void**)&cidx, g_cidx);
    cudaGetSymbolAddress((void**)&nact, g_nact);

    cudaFuncSetAttribute(gemm_mma2, cudaFuncAttributeMaxDynamicSharedMemorySize, 2 * GSTG);
    cudaFuncSetAttribute(flash_mma, cudaFuncAttributeMaxDynamicSharedMemorySize, FTOT);

    const int NX = ML * DM;
    const int NW = DM * DM;

    compact_mask<<<BB, 256>>>(mask, cidx, nact);

    split_bf16<<<NX / 1024, 256>>>(q, x0h, x0l, NX);
    split_bf16<<<NX / 1024, 256>>>(k, x1h, x1l, NX);
    split_bf16<<<NX / 1024, 256>>>(v, x2h, x2l, NX);
    split_bf16<<<NW / 1024, 256>>>(Wq, w0h, w0l, NW);
    split_bf16<<<NW / 1024, 256>>>(Wk, w1h, w1l, NW);
    split_bf16<<<NW / 1024, 256>>>(Wv, w2h, w2l, NW);

    GP p{};
    p.Ahi[0] = x0h; p.Alo[0] = x0l; p.Bhi[0] = w0h; p.Blo[0] = w0l;
    p.bias[0] = bq; p.Yhi[0] = qhi; p.Ylo[0] = qlo;
    p.scale[0] = 0.18033688011112042f;  // 0.125 * log2(e)
    p.mode[0] = 1;
    p.Ahi[1] = x1h; p.Alo[1] = x1l; p.Bhi[1] = w1h; p.Blo[1] = w1l;
    p.bias[1] = bk; p.Yf[1] = gk; p.scale[1] = 1.f; p.mode[1] = 0;
    p.Ahi[2] = x2h; p.Alo[2] = x2l; p.Bhi[2] = w2h; p.Blo[2] = w2l;
    p.bias[2] = bv; p.Yf[2] = gv; p.scale[2] = 1.f; p.mode[2] = 0;
    gemm_mma2<<<dim3(DM / 128, ML / 128, 3), 256, 2 * GSTG>>>(p);

    gather_kv<<<dim3(LL / 128, NH, BB), 256>>>(gk, gv, cidx, nact, kchi, kclo, vthi, vtlo);

    flash_mma<<<dim3(LL / 128, NH, BB), 256, FTOT>>>(qhi, qlo, kchi, kclo, vthi, vtlo,
                                                     nact, ahi, alo);

    split_bf16<<<NW / 1024, 256>>>(Wo, w0h, w0l, NW);
    GP p2{};
    p2.Ahi[0] = ahi; p2.Alo[0] = alo; p2.Bhi[0] = w0h; p2.Blo[0] = w0l;
    p2.bias[0] = bo; p2.Yf[0] = (float*)d_out; p2.scale[0] = 1.f; p2.mode[0] = 0;
    gemm_mma2<<<dim3(DM / 128, ML / 128, 1), 256, 2 * GSTG>>>(p2);
}

// round 11
// speedup vs baseline: 4.9423x; 1.2519x over previous
#include <cuda_runtime.h>
#include <cuda_bf16.h>
#include <cstdint>

#define DM 1024
#define NH 16
#define HD 64
#define BB 2
#define LL 2048
#define ML (BB * LL)  // 4096 total rows

// ---------------- scratch (no allocation allowed) ----------------
__device__ __nv_bfloat16 g_x0hi[ML * DM], g_x0lo[ML * DM];
__device__ __nv_bfloat16 g_x1hi[ML * DM], g_x1lo[ML * DM];
__device__ __nv_bfloat16 g_x2hi[ML * DM], g_x2lo[ML * DM];
__device__ __nv_bfloat16 g_w0hi[DM * DM], g_w0lo[DM * DM];
__device__ __nv_bfloat16 g_w1hi[DM * DM], g_w1lo[DM * DM];
__device__ __nv_bfloat16 g_w2hi[DM * DM], g_w2lo[DM * DM];
__device__ __nv_bfloat16 g_w3hi[DM * DM], g_w3lo[DM * DM];
__device__ __nv_bfloat16 g_qhi[ML * DM], g_qlo[ML * DM];
__device__ __nv_bfloat16 g_kchi[BB * NH * LL * HD], g_kclo[BB * NH * LL * HD];
__device__ __nv_bfloat16 g_vchi[BB * NH * LL * HD], g_vclo[BB * NH * LL * HD];
__device__ __nv_bfloat16 g_vthi[BB * NH * HD * LL], g_vtlo[BB * NH * HD * LL];
__device__ __nv_bfloat16 g_ahi[ML * DM], g_alo[ML * DM];  // flash output (split)
__device__ int g_cidx[BB * LL];
__device__ int g_nact[BB];

// ================= helpers (base compute_103 PTX only) ==========
__device__ __forceinline__ uint32_t smem_u32(const void* p) {
    uint32_t a;
    asm("{ .reg .u64 t; cvta.to.shared.u64 t, %1; cvt.u32.u64 %0, t; }" : "=r"(a) : "l"(p));
    return a;
}
__device__ __forceinline__ void ldm_x4(uint32_t* r, uint32_t addr) {
    asm volatile("ldmatrix.sync.aligned.m8n8.x4.shared.b16 {%0,%1,%2,%3}, [%4];"
                 : "=r"(r[0]), "=r"(r[1]), "=r"(r[2]), "=r"(r[3]) : "r"(addr));
}
__device__ __forceinline__ void ldm_x2(uint32_t* r, uint32_t addr) {
    asm volatile("ldmatrix.sync.aligned.m8n8.x2.shared.b16 {%0,%1}, [%2];"
                 : "=r"(r[0]), "=r"(r[1]) : "r"(addr));
}
__device__ __forceinline__ void mma16816(float* c, const uint32_t* a, const uint32_t* b) {
    asm volatile("mma.sync.aligned.m16n8k16.row.col.f32.bf16.bf16.f32 "
                 "{%0,%1,%2,%3}, {%4,%5,%6,%7}, {%8,%9}, {%0,%1,%2,%3};"
                 : "+f"(c[0]), "+f"(c[1]), "+f"(c[2]), "+f"(c[3])
                 : "r"(a[0]), "r"(a[1]), "r"(a[2]), "r"(a[3]), "r"(b[0]), "r"(b[1]));
}
__device__ __forceinline__ float ex2(float x) {
    float y;
    asm("ex2.approx.ftz.f32 %0, %1;" : "=f"(y) : "f"(x));
    return y;
}
__device__ __forceinline__ uint32_t pack2(__nv_bfloat16 a, __nv_bfloat16 b) {
    __nv_bfloat162 t = __halves2bfloat162(a, b);
    return *reinterpret_cast<uint32_t*>(&t);
}
#define CP16(d, s) asm volatile("cp.async.cg.shared.global [%0], [%1], 16;" :: "r"(d), "l"(s))
#define CPCOMMIT() asm volatile("cp.async.commit_group;" ::: "memory")
#define CPWAIT0()  asm volatile("cp.async.wait_group 0;" ::: "memory")

// =================================================================
// split fp32 -> bf16 hi/lo
// =================================================================
__global__ __launch_bounds__(256)
void split_bf16(const float* __restrict__ x, __nv_bfloat16* __restrict__ hi,
                __nv_bfloat16* __restrict__ lo, int n)
{
    int i = (blockIdx.x * 256 + threadIdx.x) * 4;
    if (i >= n) return;
    float4 f = *reinterpret_cast<const float4*>(x + i);
    __nv_bfloat16 h0 = __float2bfloat16(f.x);
    __nv_bfloat16 h1 = __float2bfloat16(f.y);
    __nv_bfloat16 h2 = __float2bfloat16(f.z);
    __nv_bfloat16 h3 = __float2bfloat16(f.w);
    *reinterpret_cast<__nv_bfloat162*>(hi + i)     = __nv_bfloat162(h0, h1);
    *reinterpret_cast<__nv_bfloat162*>(hi + i + 2) = __nv_bfloat162(h2, h3);
    *reinterpret_cast<__nv_bfloat162*>(lo + i) = __nv_bfloat162(
        __float2bfloat16(f.x - __bfloat162float(h0)),
        __float2bfloat16(f.y - __bfloat162float(h1)));
    *reinterpret_cast<__nv_bfloat162*>(lo + i + 2) = __nv_bfloat162(
        __float2bfloat16(f.z - __bfloat162float(h2)),
        __float2bfloat16(f.w - __bfloat162float(h3)));
}

// =================================================================
// mask compaction (deterministic)
// =================================================================
__global__ __launch_bounds__(256)
void compact_mask(const int* __restrict__ mask, int* __restrict__ cidx,
                  int* __restrict__ nact)
{
    int b = blockIdx.x, tid = threadIdx.x;
    __shared__ int ws[256];
    const int* mb = mask + b * LL;
    int base = tid * 8;
    int loc[8];
    int cnt = 0;
#pragma unroll
    for (int i = 0; i < 8; i++) { loc[i] = cnt; cnt += (mb[base + i] == 0); }
    ws[tid] = cnt;
    __syncthreads();
    if (tid == 0) {
        int acc = 0;
        for (int i = 0; i < 256; i++) { int t = ws[i]; ws[i] = acc; acc += t; }
        nact[b] = acc;
    }
    __syncthreads();
    int off = ws[tid];
#pragma unroll
    for (int i = 0; i < 8; i++)
        if (mb[base + i] == 0) cidx[b * LL + off + loc[i]] = base + i;
}

// =================================================================
// cp.async double-buffered GEMM, batched over z.
// mode 0: fp32 out; mode 1: bf16 split, scaled, [row][DM];
// mode 2: bf16 split, compact head layout [b,h][key][HD].
// gather: A rows come from per-batch compacted key indices.
// =================================================================
#define LDK 40
#define GSTG 40960

struct GP {
    const __nv_bfloat16 *Ahi[3], *Alo[3], *Bhi[3], *Blo[3];
    const float* bias[3];
    float* Yf[3];
    __nv_bfloat16 *Yhi[3], *Ylo[3];
    float scale[3];
    int mode[3];
    int gather[3];
    const int* cidx;
    const int* nact;
};

__global__ __launch_bounds__(256)
void gemm_mma2(GP p)
{
    extern __shared__ char smem[];
    __shared__ int sidx[128];
    const int z = blockIdx.z;
    const __nv_bfloat16* __restrict__ Ahi = p.Ahi[z];
    const __nv_bfloat16* __restrict__ Alo = p.Alo[z];
    const __nv_bfloat16* __restrict__ Bhi = p.Bhi[z];
    const __nv_bfloat16* __restrict__ Blo = p.Blo[z];
    const float* __restrict__ bias = p.bias[z];

    const int tid = threadIdx.x, lane = tid & 31, wid = tid >> 5;
    const int wm = wid & 1, wn = wid >> 1;
    const int bm = blockIdx.y * 128, bn = blockIdx.x * 128;
    const int gflag = p.gather[z];
    const int b = bm >> 11;  // batch (LL=2048)
    const uint32_t su = smem_u32(smem);

    if (gflag) {
        int na = p.nact[b];
        int bound = (na + 63) & ~63;
        int gi0 = bm & (LL - 1);
        if (gi0 >= bound) return;
        if (tid < 128) {
            int gi = gi0 + tid;
            int gcl = gi < na ? gi : na - 1;
            sidx[tid] = p.cidx[b * LL + gcl];
        }
        __syncthreads();
    }

    float acc[4][4][4];
#pragma unroll
    for (int mt = 0; mt < 4; mt++)
#pragma unroll
        for (int nt = 0; nt < 4; nt++)
#pragma unroll
            for (int e = 0; e < 4; e++) acc[mt][nt][e] = 0.f;

    const uint32_t aoff = (uint32_t)(((lane & 15) * LDK + (lane >> 4) * 8) * 2);
    const uint32_t boff = (uint32_t)(((lane & 7) * LDK + ((lane >> 3) & 1) * 8) * 2);

    auto issue = [&](int s, int c) {
        uint32_t sb = su + (uint32_t)s * GSTG;
        int k0 = c * 32;
#pragma unroll
        for (int rep = 0; rep < 2; rep++) {
            int ch = tid + rep * 256;              // 0..511: 128 rows x 4 segs (64B/row)
            int row = ch >> 2, seg = ch & 3;
            uint32_t doff = (uint32_t)(row * 80 + seg * 16);
            size_t arow = gflag ? (size_t)(b * LL + sidx[row]) : (size_t)(bm + row);
            size_t goA = arow * DM + k0 + seg * 8;
            size_t goB = (size_t)(bn + row) * DM + k0 + seg * 8;
            CP16(sb + doff,         Ahi + goA);
            CP16(sb + 10240 + doff, Alo + goA);
            CP16(sb + 20480 + doff, Bhi + goB);
            CP16(sb + 30720 + doff, Blo + goB);
        }
    };

    issue(0, 0);
    CPCOMMIT();

    for (int c = 0; c < 32; c++) {
        CPWAIT0();
        __syncthreads();
        if (c + 1 < 32) { issue((c + 1) & 1, c + 1); CPCOMMIT(); }
        const uint32_t sb = su + (uint32_t)(c & 1) * GSTG;
        const uint32_t uAh = sb, uAl = sb + 10240, uBh = sb + 20480, uBl = sb + 30720;
#pragma unroll
        for (int ks = 0; ks < 2; ks++) {
            const uint32_t kb = (uint32_t)(ks * 32);
            uint32_t ah[4][4], al[4][4], bh[4][2], bl[4][2];
#pragma unroll
            for (int mt = 0; mt < 4; mt++) {
                uint32_t r = (uint32_t)((wm * 64 + mt * 16) * LDK * 2) + aoff + kb;
                ldm_x4(ah[mt], uAh + r);
                ldm_x4(al[mt], uAl + r);
            }
#pragma unroll
            for (int nt = 0; nt < 4; nt++) {
                uint32_t r = (uint32_t)((wn * 32 + nt * 8) * LDK * 2) + boff + kb;
                ldm_x2(bh[nt], uBh + r);
                ldm_x2(bl[nt], uBl + r);
            }
#pragma unroll
            for (int mt = 0; mt < 4; mt++)
#pragma unroll
                for (int nt = 0; nt < 4; nt++) {
                    mma16816(acc[mt][nt], ah[mt], bh[nt]);
                    mma16816(acc[mt][nt], ah[mt], bl[nt]);
                    mma16816(acc[mt][nt], al[mt], bh[nt]);
                }
        }
    }

    const int mode = p.mode[z];
    if (mode == 0) {
        float* Y = p.Yf[z];
#pragma unroll
        for (int mt = 0; mt < 4; mt++) {
            int r0 = bm + wm * 64 + mt * 16 + (lane >> 2);
#pragma unroll
            for (int nt = 0; nt < 4; nt++) {
                int c0 = bn + wn * 32 + nt * 8 + (lane & 3) * 2;
                float bx = bias[c0], by = bias[c0 + 1];
                *reinterpret_cast<float2*>(Y + (size_t)r0 * DM + c0) =
                    make_float2(acc[mt][nt][0] + bx, acc[mt][nt][1] + by);
                *reinterpret_cast<float2*>(Y + (size_t)(r0 + 8) * DM + c0) =
                    make_float2(acc[mt][nt][2] + bx, acc[mt][nt][3] + by);
            }
        }
    } else if (mode == 1) {
        __nv_bfloat16* Yh = p.Yhi[z];
        __nv_bfloat16* Yl = p.Ylo[z];
        const float sc = p.scale[z];
#pragma unroll
        for (int mt = 0; mt < 4; mt++) {
            int r0 = bm + wm * 64 + mt * 16 + (lane >> 2);
#pragma unroll
            for (int nt = 0; nt < 4; nt++) {
                int c0 = bn + wn * 32 + nt * 8 + (lane & 3) * 2;
                float bx = bias[c0], by = bias[c0 + 1];
                float y0 = (acc[mt][nt][0] + bx) * sc;
                float y1 = (acc[mt][nt][1] + by) * sc;
                float y2 = (acc[mt][nt][2] + bx) * sc;
                float y3 = (acc[mt][nt][3] + by) * sc;
                __nv_bfloat16 h0 = __float2bfloat16(y0), h1 = __float2bfloat16(y1);
                __nv_bfloat16 h2 = __float2bfloat16(y2), h3 = __float2bfloat16(y3);
                *reinterpret_cast<uint32_t*>(Yh + (size_t)r0 * DM + c0) = pack2(h0, h1);
                *reinterpret_cast<uint32_t*>(Yh + (size_t)(r0 + 8) * DM + c0) = pack2(h2, h3);
                *reinterpret_cast<uint32_t*>(Yl + (size_t)r0 * DM + c0) =
                    pack2(__float2bfloat16(y0 - __bfloat162float(h0)),
                          __float2bfloat16(y1 - __bfloat162float(h1)));
                *reinterpret_cast<uint32_t*>(Yl + (size_t)(r0 + 8) * DM + c0) =
                    pack2(__float2bfloat16(y2 - __bfloat162float(h2)),
                          __float2bfloat16(y3 - __bfloat162float(h3)));
            }
        }
    } else {  // mode 2: compact head layout [b,h][key][HD]
        __nv_bfloat16* Yh = p.Yhi[z];
        __nv_bfloat16* Yl = p.Ylo[z];
#pragma unroll
        for (int mt = 0; mt < 4; mt++) {
            int r0 = bm + wm * 64 + mt * 16 + (lane >> 2);
            int key = r0 & (LL - 1);
#pragma unroll
            for (int nt = 0; nt < 4; nt++) {
                int c0 = bn + wn * 32 + nt * 8 + (lane & 3) * 2;
                int hh = c0 >> 6, d = c0 & 63;
                size_t base = ((size_t)(b * NH + hh) * LL + key) * HD + d;
                float bx = bias[c0], by = bias[c0 + 1];
                float y0 = acc[mt][nt][0] + bx;
                float y1 = acc[mt][nt][1] + by;
                float y2 = acc[mt][nt][2] + bx;
                float y3 = acc[mt][nt][3] + by;
                __nv_bfloat16 h0 = __float2bfloat16(y0), h1 = __float2bfloat16(y1);
                __nv_bfloat16 h2 = __float2bfloat16(y2), h3 = __float2bfloat16(y3);
                *reinterpret_cast<uint32_t*>(Yh + base) = pack2(h0, h1);
                *reinterpret_cast<uint32_t*>(Yh + base + 8 * HD) = pack2(h2, h3);
                *reinterpret_cast<uint32_t*>(Yl + base) =
                    pack2(__float2bfloat16(y0 - __bfloat162float(h0)),
                          __float2bfloat16(y1 - __bfloat162float(h1)));
                *reinterpret_cast<uint32_t*>(Yl + base + 8 * HD) =
                    pack2(__float2bfloat16(y2 - __bfloat162float(h2)),
                          __float2bfloat16(y3 - __bfloat162float(h3)));
            }
        }
    }
}

// =================================================================
// V transpose: [b,h][key][HD] bf16 -> [b,h][HD][key] bf16 (hi and lo)
// =================================================================
__global__ __launch_bounds__(256)
void vtrans(const __nv_bfloat16* __restrict__ Vc, const __nv_bfloat16* __restrict__ Vcl,
            const int* __restrict__ nact,
            __nv_bfloat16* __restrict__ Vth, __nv_bfloat16* __restrict__ Vtl)
{
    __shared__ __nv_bfloat16 sh[128 * 72];
    const int it = blockIdx.x, h = blockIdx.y, b = blockIdx.z;
    const int bh = b * NH + h;
    const int na = nact[b];
    const int bound = (na + 63) & ~63;
    const int k0 = it * 128;
    if (k0 >= bound) return;
    const int tid = threadIdx.x;
    const int d = tid >> 2, ks = (tid & 3) * 32;

#pragma unroll
    for (int ps = 0; ps < 2; ps++) {
        const __nv_bfloat16* src = ps ? Vcl : Vc;
        __nv_bfloat16* dst = ps ? Vtl : Vth;
        if (ps) __syncthreads();
        for (int i = tid; i < 128 * 8; i += 256) {
            int row = i >> 3, seg = i & 7;
            *reinterpret_cast<float4*>(&sh[row * 72 + seg * 8]) =
                *reinterpret_cast<const float4*>(src + ((size_t)bh * LL + k0 + row) * HD + seg * 8);
        }
        __syncthreads();
        __nv_bfloat16 buf[32];
#pragma unroll
        for (int j = 0; j < 32; j++) buf[j] = sh[(ks + j) * 72 + d];
        float4* dp = reinterpret_cast<float4*>(dst + ((size_t)bh * HD + d) * LL + k0 + ks);
        const float4* bp = reinterpret_cast<const float4*>(buf);
#pragma unroll
        for (int j = 0; j < 4; j++) dp[j] = bp[j];
    }
}

// =================================================================
// Flash attention, mma.sync + cp.async double-buffered K/V tiles.
// =================================================================
#define FQH 0
#define FQL 18432
#define FSB 36864
#define FSTG 36864
#define FTOT (FSB + 2 * FSTG)  // 110592

__global__ __launch_bounds__(256)
void flash_mma(const __nv_bfloat16* __restrict__ Qhi, const __nv_bfloat16* __restrict__ Qlo,
               const __nv_bfloat16* __restrict__ Kchi, const __nv_bfloat16* __restrict__ Kclo,
               const __nv_bfloat16* __restrict__ Vthi, const __nv_bfloat16* __restrict__ Vtlo,
               const int* __restrict__ nact,
               __nv_bfloat16* __restrict__ Ohi, __nv_bfloat16* __restrict__ Olo)
{
    extern __shared__ char smem[];
    const int qt = blockIdx.x, h = blockIdx.y, b = blockIdx.z;
    const int tid = threadIdx.x, lane = tid & 31, w = tid >> 5;
    const int bh = b * NH + h;
    const int na = nact[b];
    const int ktiles = (na + 63) >> 6;
    const uint32_t su = smem_u32(smem);

    {
        const __nv_bfloat16* qh = Qhi + ((size_t)(b * LL + qt * 128)) * DM + h * HD;
        const __nv_bfloat16* ql = Qlo + ((size_t)(b * LL + qt * 128)) * DM + h * HD;
        for (int idx = tid; idx < 1024; idx += 256) {
            int row = idx >> 3, seg = idx & 7;
            *reinterpret_cast<float4*>(smem + FQH + row * 144 + seg * 16) =
                *reinterpret_cast<const float4*>(qh + (size_t)row * DM + seg * 8);
            *reinterpret_cast<float4*>(smem + FQL + row * 144 + seg * 16) =
                *reinterpret_cast<const float4*>(ql + (size_t)row * DM + seg * 8);
        }
    }

    auto issue = [&](int s, int kt) {
        uint32_t sb = su + FSB + (uint32_t)s * FSTG;
        const __nv_bfloat16* kh = Kchi + ((size_t)bh * LL + kt * 64) * HD;
        const __nv_bfloat16* kl = Kclo + ((size_t)bh * LL + kt * 64) * HD;
        const __nv_bfloat16* vh = Vthi + (size_t)bh * HD * LL + kt * 64;
        const __nv_bfloat16* vl = Vtlo + (size_t)bh * HD * LL + kt * 64;
#pragma unroll
        for (int rep = 0; rep < 2; rep++) {
            int ch = tid + rep * 256;
            int row = ch >> 3, seg = ch & 7;
            uint32_t doff = (uint32_t)(row * 144 + seg * 16);
            CP16(sb + doff,          kh + (size_t)row * HD + seg * 8);
            CP16(sb + 9216 + doff,   kl + (size_t)row * HD + seg * 8);
            CP16(sb + 18432 + doff,  vh + (size_t)row * LL + seg * 8);
            CP16(sb + 27648 + doff,  vl + (size_t)row * LL + seg * 8);
        }
    };

    float m0 = -3.0e38f, m1 = -3.0e38f, l0 = 0.f, l1 = 0.f;
    float oacc[8][4];
#pragma unroll
    for (int nt = 0; nt < 8; nt++)
#pragma unroll
        for (int e = 0; e < 4; e++) oacc[nt][e] = 0.f;

    const uint32_t qaoff = (uint32_t)(((lane & 15) * 72 + (lane >> 4) * 8) * 2);
    const uint32_t boff  = (uint32_t)(((lane & 7) * 72 + ((lane >> 3) & 1) * 8) * 2);
    const uint32_t qrowoff = (uint32_t)(w * 16 * 144);

    issue(0, 0);
    CPCOMMIT();

    for (int kt = 0; kt < ktiles; kt++) {
        CPWAIT0();
        __syncthreads();
        if (kt + 1 < ktiles) { issue((kt + 1) & 1, kt + 1); CPCOMMIT(); }
        const uint32_t sb = su + FSB + (uint32_t)(kt & 1) * FSTG;
        const uint32_t uKH = sb, uKL = sb + 9216, uVH = sb + 18432, uVL = sb + 27648;

        float sacc[8][4];
#pragma unroll
        for (int nt = 0; nt < 8; nt++)
#pragma unroll
            for (int e = 0; e < 4; e++) sacc[nt][e] = 0.f;

#pragma unroll
        for (int ks = 0; ks < 4; ks++) {
            uint32_t ah[4], al[4];
            ldm_x4(ah, su + FQH + qrowoff + qaoff + ks * 32);
            ldm_x4(al, su + FQL + qrowoff + qaoff + ks * 32);
#pragma unroll
            for (int nt = 0; nt < 8; nt++) {
                uint32_t bh2[2], bl2[2];
                ldm_x2(bh2, uKH + nt * 1152 + boff + ks * 32);
                ldm_x2(bl2, uKL + nt * 1152 + boff + ks * 32);
                mma16816(sacc[nt], ah, bh2);
                mma16816(sacc[nt], ah, bl2);
                mma16816(sacc[nt], al, bh2);
            }
        }

        if (kt == ktiles - 1) {
            int jb = kt * 64 + 2 * (lane & 3);
#pragma unroll
            for (int nt = 0; nt < 8; nt++) {
                if (jb + nt * 8     >= na) { sacc[nt][0] = -1e30f; sacc[nt][2] = -1e30f; }
                if (jb + nt * 8 + 1 >= na) { sacc[nt][1] = -1e30f; sacc[nt][3] = -1e30f; }
            }
        }

        float rm0 = -3.0e38f, rm1 = -3.0e38f;
#pragma unroll
        for (int nt = 0; nt < 8; nt++) {
            rm0 = fmaxf(rm0, fmaxf(sacc[nt][0], sacc[nt][1]));
            rm1 = fmaxf(rm1, fmaxf(sacc[nt][2], sacc[nt][3]));
        }
        rm0 = fmaxf(rm0, __shfl_xor_sync(0xffffffffu, rm0, 1));
        rm0 = fmaxf(rm0, __shfl_xor_sync(0xffffffffu, rm0, 2));
        rm1 = fmaxf(rm1, __shfl_xor_sync(0xffffffffu, rm1, 1));
        rm1 = fmaxf(rm1, __shfl_xor_sync(0xffffffffu, rm1, 2));
        float mn0 = fmaxf(m0, rm0), mn1 = fmaxf(m1, rm1);
        float c0 = ex2(m0 - mn0), c1 = ex2(m1 - mn1);
        m0 = mn0; m1 = mn1;

        float rs0 = 0.f, rs1 = 0.f;
        uint32_t pah[4][4], pal[4][4];
#pragma unroll
        for (int t = 0; t < 4; t++) {
#pragma unroll
            for (int e = 0; e < 2; e++) {
                int nt = 2 * t + e;
                float p0 = ex2(sacc[nt][0] - mn0);
                float p1 = ex2(sacc[nt][1] - mn0);
                float p2 = ex2(sacc[nt][2] - mn1);
                float p3 = ex2(sacc[nt][3] - mn1);
                rs0 += p0 + p1;
                rs1 += p2 + p3;
                __nv_bfloat16 h0 = __float2bfloat16(p0), h1 = __float2bfloat16(p1);
                __nv_bfloat16 h2 = __float2bfloat16(p2), h3 = __float2bfloat16(p3);
                pah[t][2 * e]     = pack2(h0, h1);
                pah[t][2 * e + 1] = pack2(h2, h3);
                pal[t][2 * e]     = pack2(__float2bfloat16(p0 - __bfloat162float(h0)),
                                          __float2bfloat16(p1 - __bfloat162float(h1)));
                pal[t][2 * e + 1] = pack2(__float2bfloat16(p2 - __bfloat162float(h2)),
                                          __float2bfloat16(p3 - __bfloat162float(h3)));
            }
        }
        rs0 += __shfl_xor_sync(0xffffffffu, rs0, 1);
        rs0 += __shfl_xor_sync(0xffffffffu, rs0, 2);
        rs1 += __shfl_xor_sync(0xffffffffu, rs1, 1);
        rs1 += __shfl_xor_sync(0xffffffffu, rs1, 2);
        l0 = l0 * c0 + rs0;
        l1 = l1 * c1 + rs1;
#pragma unroll
        for (int nt = 0; nt < 8; nt++) {
            oacc[nt][0] *= c0; oacc[nt][1] *= c0;
            oacc[nt][2] *= c1; oacc[nt][3] *= c1;
        }

#pragma unroll
        for (int t = 0; t < 4; t++) {
#pragma unroll
            for (int nt = 0; nt < 8; nt++) {
                uint32_t bvh[2], bvl[2];
                ldm_x2(bvh, uVH + nt * 1152 + boff + t * 32);
                ldm_x2(bvl, uVL + nt * 1152 + boff + t * 32);
                mma16816(oacc[nt], pah[t], bvh);
                mma16816(oacc[nt], pah[t], bvl);
                mma16816(oacc[nt], pal[t], bvh);
            }
        }
    }

    float i0 = 1.f / l0, i1 = 1.f / l1;
    int r = lane >> 2;
    size_t row0 = (size_t)b * LL + qt * 128 + w * 16 + r;
    int cc0 = h * HD + 2 * (lane & 3);
#pragma unroll
    for (int nt = 0; nt < 8; nt++) {
        int cc = cc0 + nt * 8;
        float y0 = oacc[nt][0] * i0, y1 = oacc[nt][1] * i0;
        float y2 = oacc[nt][2] * i1, y3 = oacc[nt][3] * i1;
        __nv_bfloat16 h0 = __float2bfloat16(y0), h1 = __float2bfloat16(y1);
        __nv_bfloat16 h2 = __float2bfloat16(y2), h3 = __float2bfloat16(y3);
        *reinterpret_cast<uint32_t*>(Ohi + row0 * DM + cc) = pack2(h0, h1);
        *reinterpret_cast<uint32_t*>(Ohi + (row0 + 8) * DM + cc) = pack2(h2, h3);
        *reinterpret_cast<uint32_t*>(Olo + row0 * DM + cc) =
            pack2(__float2bfloat16(y0 - __bfloat162float(h0)),
                  __float2bfloat16(y1 - __bfloat162float(h1)));
        *reinterpret_cast<uint32_t*>(Olo + (row0 + 8) * DM + cc) =
            pack2(__float2bfloat16(y2 - __bfloat162float(h2)),
                  __float2bfloat16(y3 - __bfloat162float(h3)));
    }
}

// =================================================================
// launch
// =================================================================
extern "C" void kernel_launch(void* const* d_in, const int* in_sizes, int n_in,
                              void* d_out, int out_size)
{
    const float* q    = (const float*)d_in[0];
    const float* k    = (const float*)d_in[1];
    const float* v    = (const float*)d_in[2];
    const int*   mask = (const int*)d_in[3];
    const float* Wq   = (const float*)d_in[4];
    const float* bq   = (const float*)d_in[5];
    const float* Wk   = (const float*)d_in[6];
    const float* bk   = (const float*)d_in[7];
    const float* Wv   = (const float*)d_in[8];
    const float* bv   = (const float*)d_in[9];
    const float* Wo   = (const float*)d_in[10];
    const float* bo   = (const float*)d_in[11];

    __nv_bfloat16 *x0h, *x0l, *x1h, *x1l, *x2h, *x2l;
    __nv_bfloat16 *w0h, *w0l, *w1h, *w1l, *w2h, *w2l, *w3h, *w3l;
    __nv_bfloat16 *qhi, *qlo, *kchi, *kclo, *vchi, *vclo, *vthi, *vtlo, *ahi, *alo;
    int *cidx, *nact;
    cudaGetSymbolAddress((void**)&x0h, g_x0hi); cudaGetSymbolAddress((void**)&x0l, g_x0lo);
    cudaGetSymbolAddress((void**)&x1h, g_x1hi); cudaGetSymbolAddress((void**)&x1l, g_x1lo);
    cudaGetSymbolAddress((void**)&x2h, g_x2hi); cudaGetSymbolAddress((void**)&x2l, g_x2lo);
    cudaGetSymbolAddress((void**)&w0h, g_w0hi); cudaGetSymbolAddress((void**)&w0l, g_w0lo);
    cudaGetSymbolAddress((void**)&w1h, g_w1hi); cudaGetSymbolAddress((void**)&w1l, g_w1lo);
    cudaGetSymbolAddress((void**)&w2h, g_w2hi); cudaGetSymbolAddress((void**)&w2l, g_w2lo);
    cudaGetSymbolAddress((void**)&w3h, g_w3hi); cudaGetSymbolAddress((void**)&w3l, g_w3lo);
    cudaGetSymbolAddress((void**)&qhi, g_qhi);  cudaGetSymbolAddress((void**)&qlo, g_qlo);
    cudaGetSymbolAddress((void**)&kchi, g_kchi); cudaGetSymbolAddress((void**)&kclo, g_kclo);
    cudaGetSymbolAddress((void**)&vchi, g_vchi); cudaGetSymbolAddress((void**)&vclo, g_vclo);
    cudaGetSymbolAddress((void**)&vthi, g_vthi); cudaGetSymbolAddress((void**)&vtlo, g_vtlo);
    cudaGetSymbolAddress((void**)&ahi, g_ahi);  cudaGetSymbolAddress((void**)&alo, g_alo);
    cudaGetSymbolAddress((void**)&cidx, g_cidx);
    cudaGetSymbolAddress((void**)&nact, g_nact);

    cudaFuncSetAttribute(gemm_mma2, cudaFuncAttributeMaxDynamicSharedMemorySize, 2 * GSTG);
    cudaFuncSetAttribute(flash_mma, cudaFuncAttributeMaxDynamicSharedMemorySize, FTOT);

    const int NX = ML * DM;
    const int NW = DM * DM;

    compact_mask<<<BB, 256>>>(mask, cidx, nact);

    split_bf16<<<NX / 1024, 256>>>(q, x0h, x0l, NX);
    split_bf16<<<NX / 1024, 256>>>(k, x1h, x1l, NX);
    split_bf16<<<NX / 1024, 256>>>(v, x2h, x2l, NX);
    split_bf16<<<NW / 1024, 256>>>(Wq, w0h, w0l, NW);
    split_bf16<<<NW / 1024, 256>>>(Wk, w1h, w1l, NW);
    split_bf16<<<NW / 1024, 256>>>(Wv, w2h, w2l, NW);
    split_bf16<<<NW / 1024, 256>>>(Wo, w3h, w3l, NW);

    GP p{};
    p.cidx = cidx; p.nact = nact;
    // z=0: Q projection -> scaled bf16 split, full rows
    p.Ahi[0] = x0h; p.Alo[0] = x0l; p.Bhi[0] = w0h; p.Blo[0] = w0l;
    p.bias[0] = bq; p.Yhi[0] = qhi; p.Ylo[0] = qlo;
    p.scale[0] = 0.18033688011112042f;  // 0.125 * log2(e)
    p.mode[0] = 1; p.gather[0] = 0;
    // z=1: K projection -> compacted rows, compact head layout
    p.Ahi[1] = x1h; p.Alo[1] = x1l; p.Bhi[1] = w1h; p.Blo[1] = w1l;
    p.bias[1] = bk; p.Yhi[1] = kchi; p.Ylo[1] = kclo;
    p.mode[1] = 2; p.gather[1] = 1;
    // z=2: V projection -> compacted rows, compact head layout
    p.Ahi[2] = x2h; p.Alo[2] = x2l; p.Bhi[2] = w2h; p.Blo[2] = w2l;
    p.bias[2] = bv; p.Yhi[2] = vchi; p.Ylo[2] = vclo;
    p.mode[2] = 2; p.gather[2] = 1;
    gemm_mma2<<<dim3(DM / 128, ML / 128, 3), 256, 2 * GSTG>>>(p);

    vtrans<<<dim3(LL / 128, NH, BB), 256>>>(vchi, vclo, nact, vthi, vtlo);

    flash_mma<<<dim3(LL / 128, NH, BB), 256, FTOT>>>(qhi, qlo, kchi, kclo, vthi, vtlo,
                                                     nact, ahi, alo);

    GP p2{};
    p2.cidx = cidx; p2.nact = nact;
    p2.Ahi[0] = ahi; p2.Alo[0] = alo; p2.Bhi[0] = w3h; p2.Blo[0] = w3l;
    p2.bias[0] = bo; p2.Yf[0] = (float*)d_out; p2.mode[0] = 0; p2.gather[0] = 0;
    gemm_mma2<<<dim3(DM / 128, ML / 128, 1), 256, 2 * GSTG>>>(p2);
}